// round 12
// baseline (speedup 1.0000x reference)
#include <cuda_runtime.h>
#include <cstdint>
#include <cstddef>

#define TOKENS   131072
#define CDIM     96
#define NWIN     512
#define NTOK     256
#define HD       24
#define NHEADS   4
#define HIDDEN_DIM 384

typedef unsigned long long ull;

// Scratch (device globals)
__device__ float g_qkv [(size_t)3 * TOKENS * CDIM];
__device__ float g_attn[(size_t)TOKENS * CDIM];
__device__ float g_x2  [(size_t)TOKENS * CDIM];
__device__ float g_h   [(size_t)TOKENS * HIDDEN_DIM];

__device__ __forceinline__ int nat_index(int t) {
    int r = t & 255, w = t >> 8;
    int b = w >> 8, wi = w & 255;
    int d  = ((((wi >> 6) & 3) << 2) | ((r >> 6) & 3));
    int hh = ((((wi >> 4) & 3) << 2) | ((r >> 4) & 3));
    int ww = ((((wi >> 2) & 3) << 2) | ((r >> 2) & 3));
    int tt = (((wi & 3) << 2) | (r & 3));
    d = (d + 2) & 15; hh = (hh + 2) & 15; ww = (ww + 2) & 15; tt = (tt + 2) & 15;
    return (((b * 16 + d) * 16 + hh) * 16 + ww) * 16 + tt;
}

__device__ __forceinline__ int group_of(int wi, int r) {
    int g = 0;
#pragma unroll
    for (int a = 3; a >= 0; --a) {
        int c = ((((wi >> (2 * a)) & 3) << 2) | ((r >> (2 * a)) & 3));
        int s = (c < 12) ? 0 : ((c < 14) ? 1 : 2);
        g = g * 3 + s;
    }
    return g;
}

__device__ __forceinline__ void mma_tf32(float4& d, const uint32_t a[4], const uint32_t b[2]) {
    asm("mma.sync.aligned.m16n8k8.row.col.f32.tf32.tf32.f32 "
        "{%0,%1,%2,%3},{%4,%5,%6,%7},{%8,%9},{%0,%1,%2,%3};"
        : "+f"(d.x), "+f"(d.y), "+f"(d.z), "+f"(d.w)
        : "r"(a[0]), "r"(a[1]), "r"(a[2]), "r"(a[3]), "r"(b[0]), "r"(b[1]));
}

// cp.async helpers
__device__ __forceinline__ void cp16(uint32_t dst, const void* src) {
    asm volatile("cp.async.cg.shared.global [%0],[%1],16;" :: "r"(dst), "l"(src));
}
__device__ __forceinline__ void cp_commit() { asm volatile("cp.async.commit_group;"); }
template <int N>
__device__ __forceinline__ void cp_wait() { asm volatile("cp.async.wait_group %0;" :: "n"(N)); }

// wait until groups A..W_nb are complete (pending <= NB-1-nb)
template <int NB>
__device__ __forceinline__ void wait_nb(int nb) {
    int p = NB - 1 - nb;
    if (p <= 0)      cp_wait<0>();
    else if (p == 1) cp_wait<1>();
    else if (p == 2) cp_wait<2>();
    else             cp_wait<3>();
}

// Fast exact-enough GELU: erf via Abramowitz-Stegun 7.1.26 (|err| <= 1.5e-7).
__device__ __forceinline__ float gelu_f(float v) {
    float z = fabsf(v) * 0.70710678118654752f;
    float t = __frcp_rn(fmaf(0.3275911f, z, 1.f));
    float p = fmaf(fmaf(fmaf(fmaf(1.061405429f, t, -1.453152027f), t, 1.421413741f),
                        t, -0.284496736f), t, 0.254829592f) * t;
    float e = __expf(-z * z);
    float erf_abs = fmaf(-p, e, 1.f);
    float er = copysignf(erf_abs, v);
    return 0.5f * v * (1.f + er);
}

enum { EPI_QKV = 0, EPI_PROJ = 1, EPI_FC1 = 2, EPI_FC2 = 3 };

// ---------------------------------------------------------------------------
// W-RESIDENT tf32 GEMM: A (128x96) staged once (+optional LN/gather); ALL of
// W staged in smem as NB per-n-block cp.async groups.  Each n-block: ONE wait,
// ONE sync, then 12 ksteps x 12 mmas uninterrupted + fused epilogue.
// W chunk layout: [96 rows][32 words], 16B chunk j of row r at ((j+r)&7)
// (conflict-free b-frag loads, same as R11).
// ---------------------------------------------------------------------------
#define ASTR2 100
#define WCHW  3072   // words per 96x32 W chunk

template <int E, bool LNF, bool GATHER, int NB, int OCC>
__global__ void __launch_bounds__(256, OCC) gemm_wres(const float* __restrict__ A,
                                                      const float* __restrict__ W,
                                                      const float* __restrict__ bias,
                                                      const float* __restrict__ res,
                                                      const float* __restrict__ gamma,
                                                      const float* __restrict__ beta,
                                                      float* __restrict__ out) {
    extern __shared__ float smem[];
    float* As = smem;                         // [128][100]
    float* Wr = smem + 128 * ASTR2;           // [NB*3][WCHW]

    const int tid  = threadIdx.x;
    const int warp = tid >> 5, lane = tid & 31;
    const int gid  = lane >> 2, tig = lane & 3;
    const int wm   = (warp >> 1) * 32;
    const int wb   = warp & 1;
    const int wn   = wb * 48;
    const int m0   = blockIdx.x * 128;

    uint32_t as_u = (uint32_t)__cvta_generic_to_shared(As);
    uint32_t wr_u = (uint32_t)__cvta_generic_to_shared(Wr);

    // ---- group 0: A tile (12 cp16 / thread) ----
#pragma unroll
    for (int it = 0; it < 12; ++it) {
        int idx = tid + it * 256;
        int row = idx / 24, c4 = (idx % 24) << 2;
        int m = m0 + row;
        const float* src = A + (size_t)(GATHER ? nat_index(m) : m) * CDIM + c4;
        cp16(as_u + (row * ASTR2 + c4) * 4, src);
    }
    cp_commit();

    // ---- groups 1..NB: W per n-block (9 cp16 / thread / group) ----
    const int wrow = tid >> 3, wj = tid & 7;
#pragma unroll
    for (int nb = 0; nb < NB; ++nb) {
#pragma unroll
        for (int ch = 0; ch < 3; ++ch) {
            uint32_t wbuf = wr_u + ((nb * 3 + ch) * WCHW) * 4;
            const float* wsrc = W + (size_t)(nb * 96) * CDIM + ch * 32;
#pragma unroll
            for (int it = 0; it < 3; ++it) {
                int r = wrow + it * 32;
                cp16(wbuf + (r * 32 + (((wj + r) & 7) << 2)) * 4,
                     wsrc + (size_t)r * CDIM + (wj << 2));
            }
        }
        cp_commit();
    }

    if (LNF) {
        cp_wait<NB>();                        // A complete; W still streaming
        __syncthreads();
        int row = tid >> 1, half = tid & 1;
        float s = 0.f, sq = 0.f;
#pragma unroll
        for (int i = 0; i < 48; ++i) {
            float v = As[row * ASTR2 + half * 48 + i];
            s += v; sq += v * v;
        }
        s  += __shfl_xor_sync(0xffffffffu, s, 1);
        sq += __shfl_xor_sync(0xffffffffu, sq, 1);
        float mean = s * (1.f / 96.f);
        float var  = sq * (1.f / 96.f) - mean * mean;
        float rstd = rsqrtf(var + 1e-5f);
#pragma unroll
        for (int i = 0; i < 48; ++i) {
            int col = half * 48 + i;
            As[row * ASTR2 + col] = (As[row * ASTR2 + col] - mean) * rstd * __ldg(gamma + col) + __ldg(beta + col);
        }
    }

    const uint32_t* Asu = (const uint32_t*)As;

    float4 acc[2][6];
#pragma unroll
    for (int i = 0; i < 2; ++i)
#pragma unroll
        for (int j = 0; j < 6; ++j) acc[i][j] = make_float4(0.f, 0.f, 0.f, 0.f);

    for (int nb = 0; nb < NB; ++nb) {
        wait_nb<NB>(nb);                      // A .. W_nb complete
        __syncthreads();                      // (also publishes LN writes at nb=0)

        // 12 uninterrupted ksteps
        for (int ks = 0; ks < 12; ++ks) {
            const int kg  = ks * 8;
            const int ks4 = ks & 3;
            const uint32_t* Ws = (const uint32_t*)(Wr + (nb * 3 + (ks >> 2)) * WCHW);

            uint32_t a[2][4];
#pragma unroll
            for (int mi = 0; mi < 2; ++mi) {
                int r = wm + mi * 16 + gid;
                a[mi][0] = Asu[r * ASTR2 + kg + tig];
                a[mi][1] = Asu[(r + 8) * ASTR2 + kg + tig];
                a[mi][2] = Asu[r * ASTR2 + kg + tig + 4];
                a[mi][3] = Asu[(r + 8) * ASTR2 + kg + tig + 4];
            }
            uint32_t b[6][2];
#pragma unroll
            for (int ni = 0; ni < 6; ++ni) {
                int n = wn + ni * 8 + gid;
                int ch0 = (2 * ks4 + gid) & 7;
                int ch1 = (2 * ks4 + 1 + gid) & 7;
                b[ni][0] = Ws[n * 32 + (ch0 << 2) + tig];
                b[ni][1] = Ws[n * 32 + (ch1 << 2) + tig];
            }
#pragma unroll
            for (int mi = 0; mi < 2; ++mi)
#pragma unroll
                for (int ni = 0; ni < 6; ++ni) mma_tf32(acc[mi][ni], a[mi], b[ni]);
        }

        // ---- fused epilogue for n-block nb ----
        const int n0 = nb * 96;
#pragma unroll
        for (int mi = 0; mi < 2; ++mi) {
            int r0 = m0 + wm + mi * 16 + gid;
#pragma unroll
            for (int half = 0; half < 2; ++half) {
                int m = r0 + half * 8;
                size_t proj_dst = 0;
                if (E == EPI_PROJ) proj_dst = (size_t)nat_index(m) * CDIM;
                int w = m >> 8, rr = m & 255;
#pragma unroll
                for (int ni = 0; ni < 6; ++ni) {
                    float v0 = half ? acc[mi][ni].z : acc[mi][ni].x;
                    float v1 = half ? acc[mi][ni].w : acc[mi][ni].y;
#pragma unroll
                    for (int e = 0; e < 2; ++e) {
                        int nl = wn + ni * 8 + tig * 2 + e;
                        float v = (e ? v1 : v0) + bias[n0 + nl];
                        if (E == EPI_QKV) {
                            const float scale = (nb == 0) ? 0.20412414523193154f : 1.0f;
                            int h = nl / 24, dd = nl % 24;
                            out[(((size_t)nb * NWIN + w) * NHEADS + h) * (NTOK * HD) + rr * HD + dd] = v * scale;
                        } else if (E == EPI_PROJ) {
                            out[proj_dst + nl] = res[proj_dst + nl] + v;
                        } else if (E == EPI_FC1) {
                            out[(size_t)m * HIDDEN_DIM + n0 + nl] = gelu_f(v);
                        } else {
                            out[(size_t)m * CDIM + nl] = res[(size_t)m * CDIM + nl] + v;
                        }
                    }
                }
            }
        }
        if (nb + 1 < NB) {
#pragma unroll
            for (int i = 0; i < 2; ++i)
#pragma unroll
                for (int j = 0; j < 6; ++j) acc[i][j] = make_float4(0.f, 0.f, 0.f, 0.f);
        }
    }
}

// ---------------------------------------------------------------------------
// Streaming tf32 GEMM for fc2 (K=384) — unchanged from R11.
// ---------------------------------------------------------------------------
#define ASTR 36

__global__ void __launch_bounds__(256, 2) gemm_fc2(const float* __restrict__ A,
                                                   const float* __restrict__ W,
                                                   const float* __restrict__ bias,
                                                   const float* __restrict__ res,
                                                   float* __restrict__ out) {
    extern __shared__ float smem[];
    constexpr int ACH = 128 * ASTR, WCH = 96 * 32, STG = ACH + WCH;
    constexpr int KD = HIDDEN_DIM, NC = KD / 32, NSTG = 3, PF = 2;

    const int tid  = threadIdx.x;
    const int warp = tid >> 5, lane = tid & 31;
    const int gid  = lane >> 2, tig = lane & 3;
    const int wm   = (warp >> 1) * 32;
    const int wb   = warp & 1;
    const int wn   = wb * 48;
    const int m0   = blockIdx.x * 128;

    uint32_t smem_u = (uint32_t)__cvta_generic_to_shared(smem);
    const int crow = tid >> 3, cj = tid & 7, cc4 = cj << 2;

    auto issue = [&](int c) {
        int s = c % NSTG, kc = c * 32;
        uint32_t abuf = smem_u + (s * STG) * 4;
#pragma unroll
        for (int it = 0; it < 4; ++it) {
            int row = crow + it * 32;
            cp16(abuf + (row * ASTR + cc4) * 4, A + (size_t)(m0 + row) * KD + kc + cc4);
        }
        uint32_t wbuf = abuf + ACH * 4;
#pragma unroll
        for (int it = 0; it < 3; ++it) {
            int r = crow + it * 32;
            cp16(wbuf + (r * 32 + (((cj + r) & 7) << 2)) * 4,
                 W + (size_t)r * KD + kc + cc4);
        }
    };

    issue(0); cp_commit();
    issue(1); cp_commit();

    float4 acc[2][6];
#pragma unroll
    for (int i = 0; i < 2; ++i)
#pragma unroll
        for (int j = 0; j < 6; ++j) acc[i][j] = make_float4(0.f, 0.f, 0.f, 0.f);

    for (int c = 0; c < NC; ++c) {
        if (c + PF < NC) issue(c + PF);
        cp_commit();
        cp_wait<PF>();
        __syncthreads();

        const uint32_t* As = (const uint32_t*)(smem + (c % NSTG) * STG);
        const uint32_t* Ws = (const uint32_t*)(smem + (c % NSTG) * STG + ACH);

#pragma unroll
        for (int ks4 = 0; ks4 < 4; ++ks4) {
            const int k = ks4 * 8;
            uint32_t a[2][4];
#pragma unroll
            for (int mi = 0; mi < 2; ++mi) {
                int r = wm + mi * 16 + gid;
                a[mi][0] = As[r * ASTR + k + tig];
                a[mi][1] = As[(r + 8) * ASTR + k + tig];
                a[mi][2] = As[r * ASTR + k + tig + 4];
                a[mi][3] = As[(r + 8) * ASTR + k + tig + 4];
            }
            uint32_t b[6][2];
#pragma unroll
            for (int ni = 0; ni < 6; ++ni) {
                int n = wn + ni * 8 + gid;
                int ch0 = (2 * ks4 + gid) & 7;
                int ch1 = (2 * ks4 + 1 + gid) & 7;
                b[ni][0] = Ws[n * 32 + (ch0 << 2) + tig];
                b[ni][1] = Ws[n * 32 + (ch1 << 2) + tig];
            }
#pragma unroll
            for (int mi = 0; mi < 2; ++mi)
#pragma unroll
                for (int ni = 0; ni < 6; ++ni) mma_tf32(acc[mi][ni], a[mi], b[ni]);
        }
        __syncthreads();
    }

#pragma unroll
    for (int mi = 0; mi < 2; ++mi) {
        int r0 = m0 + wm + mi * 16 + gid;
#pragma unroll
        for (int half = 0; half < 2; ++half) {
            int m = r0 + half * 8;
#pragma unroll
            for (int ni = 0; ni < 6; ++ni) {
                float v0 = half ? acc[mi][ni].z : acc[mi][ni].x;
                float v1 = half ? acc[mi][ni].w : acc[mi][ni].y;
#pragma unroll
                for (int e = 0; e < 2; ++e) {
                    int nl = wn + ni * 8 + tig * 2 + e;
                    float v = (e ? v1 : v0) + bias[nl];
                    out[(size_t)m * CDIM + nl] = res[(size_t)m * CDIM + nl] + v;
                }
            }
        }
    }
}

// ---------------------------------------------------------------------------
// Tensor-core attention (unchanged from R9/R11).
// ---------------------------------------------------------------------------
#define QSTR 28
#define PSTR 68

__global__ void __launch_bounds__(256) attn_mma(const float* __restrict__ qkv,
                                                float* __restrict__ attnout) {
    extern __shared__ float sm[];
    float* Qs = sm;
    float* Ks = Qs + 256 * QSTR;
    float* Vs = Ks + 256 * QSTR;
    float* Ps = Vs + 256 * 24;
    float* Ls = Ps + 256 * PSTR;
    unsigned char* grp = (unsigned char*)(Ls + 512);

    const int w = blockIdx.x, h = blockIdx.y;
    const int tid = threadIdx.x, warp = tid >> 5, lane = tid & 31;
    const int gid = lane >> 2, tig = lane & 3;
    const int wm = (warp >> 1) * 64;
    const int wb = warp & 1;
    const size_t hs = (size_t)NTOK * HD;
    const float* qb = qkv + (((size_t)0 * NWIN + w) * NHEADS + h) * hs;
    const float* kg = qkv + (((size_t)1 * NWIN + w) * NHEADS + h) * hs;
    const float* vg = qkv + (((size_t)2 * NWIN + w) * NHEADS + h) * hs;

#pragma unroll
    for (int it = 0; it < 6; ++it) {
        int idx = tid + it * 256;
        int row = idx / 6, c4 = (idx % 6) * 4;
        float4 q4 = *(const float4*)(qb + row * 24 + c4);
        float4 k4 = *(const float4*)(kg + row * 24 + c4);
        float4 v4 = *(const float4*)(vg + row * 24 + c4);
        Qs[row*QSTR+c4+0]=q4.x; Qs[row*QSTR+c4+1]=q4.y; Qs[row*QSTR+c4+2]=q4.z; Qs[row*QSTR+c4+3]=q4.w;
        Ks[row*QSTR+c4+0]=k4.x; Ks[row*QSTR+c4+1]=k4.y; Ks[row*QSTR+c4+2]=k4.z; Ks[row*QSTR+c4+3]=k4.w;
        *(float4*)(Vs + row * 24 + c4) = v4;
    }
    grp[tid] = (unsigned char)group_of(w & 255, tid);
    __syncthreads();

    const uint32_t* Qu = (const uint32_t*)Qs;
    const uint32_t* Ku = (const uint32_t*)Ks;
    const uint32_t* Vu = (const uint32_t*)Vs;
    const uint32_t* Pu = (const uint32_t*)Ps;

    float4 oacc[4][3];
#pragma unroll
    for (int i = 0; i < 4; ++i)
#pragma unroll
        for (int j = 0; j < 3; ++j) oacc[i][j] = make_float4(0.f, 0.f, 0.f, 0.f);
    float rs[4][2];
#pragma unroll
    for (int i = 0; i < 4; ++i) { rs[i][0] = 0.f; rs[i][1] = 0.f; }

    for (int kb = 0; kb < 4; ++kb) {
        float4 sacc[4][4];
#pragma unroll
        for (int i = 0; i < 4; ++i)
#pragma unroll
            for (int j = 0; j < 4; ++j) sacc[i][j] = make_float4(0.f, 0.f, 0.f, 0.f);

#pragma unroll
        for (int kk = 0; kk < 3; ++kk) {
            const int k8 = kk * 8;
            uint32_t a[4][4], b[4][2];
#pragma unroll
            for (int mi = 0; mi < 4; ++mi) {
                int r = wm + mi * 16 + gid;
                a[mi][0] = Qu[r * QSTR + k8 + tig];
                a[mi][1] = Qu[(r + 8) * QSTR + k8 + tig];
                a[mi][2] = Qu[r * QSTR + k8 + tig + 4];
                a[mi][3] = Qu[(r + 8) * QSTR + k8 + tig + 4];
            }
#pragma unroll
            for (int ni = 0; ni < 4; ++ni) {
                int n = kb * 64 + wb * 32 + ni * 8 + gid;
                b[ni][0] = Ku[n * QSTR + k8 + tig];
                b[ni][1] = Ku[n * QSTR + k8 + tig + 4];
            }
#pragma unroll
            for (int mi = 0; mi < 4; ++mi)
#pragma unroll
                for (int ni = 0; ni < 4; ++ni) mma_tf32(sacc[mi][ni], a[mi], b[ni]);
        }

#pragma unroll
        for (int mi = 0; mi < 4; ++mi) {
            int r0 = wm + mi * 16 + gid;
            int rg0 = grp[r0], rg1 = grp[r0 + 8];
#pragma unroll
            for (int ni = 0; ni < 4; ++ni) {
                int cc = kb * 64 + wb * 32 + ni * 8 + 2 * tig;
                int cg0 = grp[cc], cg1 = grp[cc + 1];
                float4 s = sacc[mi][ni];
                float p00 = __expf(s.x + (cg0 == rg0 ? 0.f : -100.f));
                float p01 = __expf(s.y + (cg1 == rg0 ? 0.f : -100.f));
                float p10 = __expf(s.z + (cg0 == rg1 ? 0.f : -100.f));
                float p11 = __expf(s.w + (cg1 == rg1 ? 0.f : -100.f));
                rs[mi][0] += p00 + p01;
                rs[mi][1] += p10 + p11;
                int pc = wb * 32 + ni * 8 + 2 * tig;
                *(float2*)(Ps + r0 * PSTR + pc)       = make_float2(p00, p01);
                *(float2*)(Ps + (r0 + 8) * PSTR + pc) = make_float2(p10, p11);
            }
        }
        __syncwarp();

#pragma unroll
        for (int kk = 0; kk < 4; ++kk) {
            const int kp = wb * 32 + kk * 8;
            const int kv = kb * 64 + kp;
            uint32_t a[4][4], b[3][2];
#pragma unroll
            for (int mi = 0; mi < 4; ++mi) {
                int r = wm + mi * 16 + gid;
                a[mi][0] = Pu[r * PSTR + kp + tig];
                a[mi][1] = Pu[(r + 8) * PSTR + kp + tig];
                a[mi][2] = Pu[r * PSTR + kp + tig + 4];
                a[mi][3] = Pu[(r + 8) * PSTR + kp + tig + 4];
            }
#pragma unroll
            for (int nd = 0; nd < 3; ++nd) {
                int n = nd * 8 + gid;
                b[nd][0] = Vu[(kv + tig) * 24 + n];
                b[nd][1] = Vu[(kv + tig + 4) * 24 + n];
            }
#pragma unroll
            for (int mi = 0; mi < 4; ++mi)
#pragma unroll
                for (int nd = 0; nd < 3; ++nd) mma_tf32(oacc[mi][nd], a[mi], b[nd]);
        }
        __syncwarp();
    }

#pragma unroll
    for (int mi = 0; mi < 4; ++mi)
#pragma unroll
        for (int hf = 0; hf < 2; ++hf) {
            float v = rs[mi][hf];
            v += __shfl_xor_sync(0xffffffffu, v, 1);
            v += __shfl_xor_sync(0xffffffffu, v, 2);
            rs[mi][hf] = v;
        }
    if (tig == 0) {
#pragma unroll
        for (int mi = 0; mi < 4; ++mi) {
            Ls[wb * 256 + wm + mi * 16 + gid]     = rs[mi][0];
            Ls[wb * 256 + wm + mi * 16 + gid + 8] = rs[mi][1];
        }
    }
    __syncthreads();

    float* OS = Qs;
    const int OSTR = 26;
    if (wb == 1) {
#pragma unroll
        for (int mi = 0; mi < 4; ++mi) {
            int r0 = wm + mi * 16 + gid;
#pragma unroll
            for (int nd = 0; nd < 3; ++nd) {
                int c = nd * 8 + 2 * tig;
                *(float2*)(OS + r0 * OSTR + c)       = make_float2(oacc[mi][nd].x, oacc[mi][nd].y);
                *(float2*)(OS + (r0 + 8) * OSTR + c) = make_float2(oacc[mi][nd].z, oacc[mi][nd].w);
            }
        }
    }
    __syncthreads();
    if (wb == 0) {
#pragma unroll
        for (int mi = 0; mi < 4; ++mi) {
            int r0 = wm + mi * 16 + gid, r1 = r0 + 8;
            float inv0 = 1.f / (Ls[r0] + Ls[256 + r0]);
            float inv1 = 1.f / (Ls[r1] + Ls[256 + r1]);
#pragma unroll
            for (int nd = 0; nd < 3; ++nd) {
                int c = nd * 8 + 2 * tig;
                float2 t0 = *(float2*)(OS + r0 * OSTR + c);
                float2 t1 = *(float2*)(OS + r1 * OSTR + c);
                float* o0 = attnout + ((size_t)w * NTOK + r0) * CDIM + h * HD + c;
                float* o1 = attnout + ((size_t)w * NTOK + r1) * CDIM + h * HD + c;
                o0[0] = (oacc[mi][nd].x + t0.x) * inv0;
                o0[1] = (oacc[mi][nd].y + t0.y) * inv0;
                o1[0] = (oacc[mi][nd].z + t1.x) * inv1;
                o1[1] = (oacc[mi][nd].w + t1.y) * inv1;
            }
        }
    }
}

// ---------------------------------------------------------------------------
extern "C" void kernel_launch(void* const* d_in, const int* in_sizes, int n_in,
                              void* d_out, int out_size) {
    (void)in_sizes; (void)n_in; (void)out_size;
    const float* x       = (const float*)d_in[0];
    const float* norm1_g = (const float*)d_in[2];
    const float* norm1_b = (const float*)d_in[3];
    const float* qkv_w   = (const float*)d_in[4];
    const float* qkv_b   = (const float*)d_in[5];
    const float* proj_w  = (const float*)d_in[6];
    const float* proj_b  = (const float*)d_in[7];
    const float* norm2_g = (const float*)d_in[8];
    const float* norm2_b = (const float*)d_in[9];
    const float* fc1_w   = (const float*)d_in[10];
    const float* fc1_b   = (const float*)d_in[11];
    const float* fc2_w   = (const float*)d_in[12];
    const float* fc2_b   = (const float*)d_in[13];
    float* out = (float*)d_out;

    float *qkv, *attn, *x2, *hbuf;
    cudaGetSymbolAddress((void**)&qkv,  g_qkv);
    cudaGetSymbolAddress((void**)&attn, g_attn);
    cudaGetSymbolAddress((void**)&x2,   g_x2);
    cudaGetSymbolAddress((void**)&hbuf, g_h);

    const int qkv_smem  = (128 * ASTR2 + 3 * 3 * WCHW) * 4;   // 161792 B
    const int proj_smem = (128 * ASTR2 + 1 * 3 * WCHW) * 4;   //  88064 B
    const int fc1_smem  = (128 * ASTR2 + 4 * 3 * WCHW) * 4;   // 198656 B
    const int fc2_smem  = 3 * (128 * ASTR + 96 * 32) * 4;     //  92160 B
    cudaFuncSetAttribute((const void*)gemm_wres<EPI_QKV,  true,  true,  3, 1>, cudaFuncAttributeMaxDynamicSharedMemorySize, qkv_smem);
    cudaFuncSetAttribute((const void*)gemm_wres<EPI_PROJ, false, false, 1, 2>, cudaFuncAttributeMaxDynamicSharedMemorySize, proj_smem);
    cudaFuncSetAttribute((const void*)gemm_wres<EPI_FC1,  true,  false, 4, 1>, cudaFuncAttributeMaxDynamicSharedMemorySize, fc1_smem);
    cudaFuncSetAttribute(gemm_fc2, cudaFuncAttributeMaxDynamicSharedMemorySize, fc2_smem);

    const int attn_smem = (256 * QSTR * 2 + 256 * 24 + 256 * PSTR + 512 + 64) * 4;
    cudaFuncSetAttribute(attn_mma, cudaFuncAttributeMaxDynamicSharedMemorySize, attn_smem);

    // 1) QKV: fused LN1 + shift + partition (gather); W fully resident
    gemm_wres<EPI_QKV, true, true, 3, 1><<<1024, 256, qkv_smem>>>(
        x, qkv_w, qkv_b, nullptr, norm1_g, norm1_b, qkv);
    // 2) windowed attention on tensor cores
    attn_mma<<<dim3(NWIN, NHEADS), 256, attn_smem>>>(qkv, attn);
    // 3) proj + reverse partition/shift + residual; W resident
    gemm_wres<EPI_PROJ, false, false, 1, 2><<<1024, 256, proj_smem>>>(
        attn, proj_w, proj_b, x, nullptr, nullptr, x2);
    // 4) fc1: fused LN2 + fast GELU; W resident
    gemm_wres<EPI_FC1, true, false, 4, 1><<<1024, 256, fc1_smem>>>(
        x2, fc1_w, fc1_b, nullptr, norm2_g, norm2_b, hbuf);
    // 5) fc2 + residual -> output (streaming, unchanged)
    gemm_fc2<<<1024, 256, fc2_smem>>>(hbuf, fc2_w, fc2_b, x2, out);
}

// round 13
// speedup vs baseline: 1.1403x; 1.1403x over previous
#include <cuda_runtime.h>
#include <cstdint>
#include <cstddef>

#define TOKENS   131072
#define CDIM     96
#define NWIN     512
#define NTOK     256
#define HD       24
#define NHEADS   4
#define HIDDEN_DIM 384

typedef unsigned long long ull;

// Scratch (device globals)
__device__ float g_qkv [(size_t)3 * TOKENS * CDIM];
__device__ float g_attn[(size_t)TOKENS * CDIM];
__device__ float g_x2  [(size_t)TOKENS * CDIM];
__device__ float g_h   [(size_t)TOKENS * HIDDEN_DIM];

__device__ __forceinline__ int nat_index(int t) {
    int r = t & 255, w = t >> 8;
    int b = w >> 8, wi = w & 255;
    int d  = ((((wi >> 6) & 3) << 2) | ((r >> 6) & 3));
    int hh = ((((wi >> 4) & 3) << 2) | ((r >> 4) & 3));
    int ww = ((((wi >> 2) & 3) << 2) | ((r >> 2) & 3));
    int tt = (((wi & 3) << 2) | (r & 3));
    d = (d + 2) & 15; hh = (hh + 2) & 15; ww = (ww + 2) & 15; tt = (tt + 2) & 15;
    return (((b * 16 + d) * 16 + hh) * 16 + ww) * 16 + tt;
}

__device__ __forceinline__ int group_of(int wi, int r) {
    int g = 0;
#pragma unroll
    for (int a = 3; a >= 0; --a) {
        int c = ((((wi >> (2 * a)) & 3) << 2) | ((r >> (2 * a)) & 3));
        int s = (c < 12) ? 0 : ((c < 14) ? 1 : 2);
        g = g * 3 + s;
    }
    return g;
}

__device__ __forceinline__ void mma_tf32(float4& d, const uint32_t a[4], const uint32_t b[2]) {
    asm("mma.sync.aligned.m16n8k8.row.col.f32.tf32.tf32.f32 "
        "{%0,%1,%2,%3},{%4,%5,%6,%7},{%8,%9},{%0,%1,%2,%3};"
        : "+f"(d.x), "+f"(d.y), "+f"(d.z), "+f"(d.w)
        : "r"(a[0]), "r"(a[1]), "r"(a[2]), "r"(a[3]), "r"(b[0]), "r"(b[1]));
}

// cp.async helpers
__device__ __forceinline__ void cp16(uint32_t dst, const void* src) {
    asm volatile("cp.async.cg.shared.global [%0],[%1],16;" :: "r"(dst), "l"(src));
}
__device__ __forceinline__ void cp_commit() { asm volatile("cp.async.commit_group;"); }
template <int N>
__device__ __forceinline__ void cp_wait() { asm volatile("cp.async.wait_group %0;" :: "n"(N)); }

// Fast exact-enough GELU: erf via Abramowitz-Stegun 7.1.26 (|err| <= 1.5e-7).
__device__ __forceinline__ float gelu_f(float v) {
    float z = fabsf(v) * 0.70710678118654752f;
    float t = __frcp_rn(fmaf(0.3275911f, z, 1.f));
    float p = fmaf(fmaf(fmaf(fmaf(1.061405429f, t, -1.453152027f), t, 1.421413741f),
                        t, -0.284496736f), t, 0.254829592f) * t;
    float e = __expf(-z * z);
    float erf_abs = fmaf(-p, e, 1.f);
    float er = copysignf(erf_abs, v);
    return 0.5f * v * (1.f + er);
}

enum { EPI_QKV = 0, EPI_PROJ = 1, EPI_FC1 = 2, EPI_FC2 = 3 };

// ---------------------------------------------------------------------------
// A-resident tf32 GEMM, 3-stage W ring, SINGLE sync per chunk:
//   per chunk: wait<1> -> sync -> issue(c+2) -> 4 ksteps (48 mmas) -> epilogue
// Stage safety: issue(c+2) writes stage (c+2)%3, last read in iter c-1,
// ordered by this iter's top sync.  W chunk c has 2 full iters to land.
// ---------------------------------------------------------------------------
#define ASTR2 100

template <int E, bool LNF, bool GATHER, int NB>
__global__ void __launch_bounds__(256, 2) gemm_fz(const float* __restrict__ A,
                                                  const float* __restrict__ W,
                                                  const float* __restrict__ bias,
                                                  const float* __restrict__ res,
                                                  const float* __restrict__ gamma,
                                                  const float* __restrict__ beta,
                                                  float* __restrict__ out) {
    extern __shared__ float smem[];
    float* As   = smem;                       // [128][100]
    float* ring = smem + 128 * ASTR2;         // 3 x [96][32] swizzled W
    constexpr int WCH = 96 * 32;
    constexpr int NC  = NB * 3;

    const int tid  = threadIdx.x;
    const int warp = tid >> 5, lane = tid & 31;
    const int gid  = lane >> 2, tig = lane & 3;
    const int wm   = (warp >> 1) * 32;
    const int wb   = warp & 1;
    const int wn   = wb * 48;
    const int m0   = blockIdx.x * 128;

    uint32_t as_u   = (uint32_t)__cvta_generic_to_shared(As);
    uint32_t ring_u = (uint32_t)__cvta_generic_to_shared(ring);

    // ---- group 0: A tile ----
#pragma unroll
    for (int it = 0; it < 12; ++it) {
        int idx = tid + it * 256;
        int row = idx / 24, c4 = (idx % 24) << 2;
        int m = m0 + row;
        const float* src = A + (size_t)(GATHER ? nat_index(m) : m) * CDIM + c4;
        cp16(as_u + (row * ASTR2 + c4) * 4, src);
    }
    cp_commit();

    const int wrow = tid >> 3, wj = tid & 7;
    auto issueW = [&](int c) {
        uint32_t wbuf = ring_u + ((c % 3) * WCH) * 4;
        int n0 = (c / 3) * 96, kc = (c % 3) * 32;
#pragma unroll
        for (int it = 0; it < 3; ++it) {
            int r = wrow + it * 32;
            uint32_t dst = wbuf + (r * 32 + (((wj + r) & 7) << 2)) * 4;
            cp16(dst, W + (size_t)(n0 + r) * CDIM + kc + (wj << 2));
        }
    };
    issueW(0); cp_commit();                   // group 1
    issueW(1); cp_commit();                   // group 2

    if (LNF) {
        cp_wait<2>();                         // A complete (W0,W1 pending)
        __syncthreads();
        int row = tid >> 1, half = tid & 1;
        float s = 0.f, sq = 0.f;
#pragma unroll
        for (int i = 0; i < 48; ++i) {
            float v = As[row * ASTR2 + half * 48 + i];
            s += v; sq += v * v;
        }
        s  += __shfl_xor_sync(0xffffffffu, s, 1);
        sq += __shfl_xor_sync(0xffffffffu, sq, 1);
        float mean = s * (1.f / 96.f);
        float var  = sq * (1.f / 96.f) - mean * mean;
        float rstd = rsqrtf(var + 1e-5f);
#pragma unroll
        for (int i = 0; i < 48; ++i) {
            int col = half * 48 + i;
            As[row * ASTR2 + col] = (As[row * ASTR2 + col] - mean) * rstd * __ldg(gamma + col) + __ldg(beta + col);
        }
        // loop-top sync publishes LN writes
    }

    const uint32_t* Asu = (const uint32_t*)As;

    float4 acc[2][6];
#pragma unroll
    for (int i = 0; i < 2; ++i)
#pragma unroll
        for (int j = 0; j < 6; ++j) acc[i][j] = make_float4(0.f, 0.f, 0.f, 0.f);

    for (int c = 0; c < NC; ++c) {
        cp_wait<1>();                         // A .. W_c complete
        __syncthreads();                      // prev readers done; LN published
        if (c + 2 < NC) issueW(c + 2);
        cp_commit();                          // keep group count aligned

        const uint32_t* Ws = (const uint32_t*)(ring + (c % 3) * WCH);

#pragma unroll
        for (int ks4 = 0; ks4 < 4; ++ks4) {
            const int kg = (c % 3) * 32 + ks4 * 8;
            uint32_t a[2][4];
#pragma unroll
            for (int mi = 0; mi < 2; ++mi) {
                int r = wm + mi * 16 + gid;
                a[mi][0] = Asu[r * ASTR2 + kg + tig];
                a[mi][1] = Asu[(r + 8) * ASTR2 + kg + tig];
                a[mi][2] = Asu[r * ASTR2 + kg + tig + 4];
                a[mi][3] = Asu[(r + 8) * ASTR2 + kg + tig + 4];
            }
            uint32_t b[6][2];
#pragma unroll
            for (int ni = 0; ni < 6; ++ni) {
                int n = wn + ni * 8 + gid;
                int ch0 = (2 * ks4 + gid) & 7;
                int ch1 = (2 * ks4 + 1 + gid) & 7;
                b[ni][0] = Ws[n * 32 + (ch0 << 2) + tig];
                b[ni][1] = Ws[n * 32 + (ch1 << 2) + tig];
            }
#pragma unroll
            for (int mi = 0; mi < 2; ++mi)
#pragma unroll
                for (int ni = 0; ni < 6; ++ni) mma_tf32(acc[mi][ni], a[mi], b[ni]);
        }

        if ((c % 3) == 2) {
            const int nb = c / 3, n0 = nb * 96;
#pragma unroll
            for (int mi = 0; mi < 2; ++mi) {
                int r0 = m0 + wm + mi * 16 + gid;
#pragma unroll
                for (int half = 0; half < 2; ++half) {
                    int m = r0 + half * 8;
                    size_t proj_dst = 0;
                    if (E == EPI_PROJ) proj_dst = (size_t)nat_index(m) * CDIM;
                    int w = m >> 8, rr = m & 255;
#pragma unroll
                    for (int ni = 0; ni < 6; ++ni) {
                        float v0 = half ? acc[mi][ni].z : acc[mi][ni].x;
                        float v1 = half ? acc[mi][ni].w : acc[mi][ni].y;
#pragma unroll
                        for (int e = 0; e < 2; ++e) {
                            int nl = wn + ni * 8 + tig * 2 + e;
                            float v = (e ? v1 : v0) + bias[n0 + nl];
                            if (E == EPI_QKV) {
                                const float scale = (nb == 0) ? 0.20412414523193154f : 1.0f;
                                int h = nl / 24, dd = nl % 24;
                                out[(((size_t)nb * NWIN + w) * NHEADS + h) * (NTOK * HD) + rr * HD + dd] = v * scale;
                            } else if (E == EPI_PROJ) {
                                out[proj_dst + nl] = res[proj_dst + nl] + v;
                            } else if (E == EPI_FC1) {
                                out[(size_t)m * HIDDEN_DIM + n0 + nl] = gelu_f(v);
                            } else {
                                out[(size_t)m * CDIM + nl] = res[(size_t)m * CDIM + nl] + v;
                            }
                        }
                    }
                }
            }
            if (c + 1 < NC) {
#pragma unroll
                for (int i = 0; i < 2; ++i)
#pragma unroll
                    for (int j = 0; j < 6; ++j) acc[i][j] = make_float4(0.f, 0.f, 0.f, 0.f);
            }
        }
    }
}

// ---------------------------------------------------------------------------
// Streaming tf32 GEMM for fc2 (K=384), 3-stage ring, single sync per chunk.
// ---------------------------------------------------------------------------
#define ASTR 36

__global__ void __launch_bounds__(256, 2) gemm_fc2(const float* __restrict__ A,
                                                   const float* __restrict__ W,
                                                   const float* __restrict__ bias,
                                                   const float* __restrict__ res,
                                                   float* __restrict__ out) {
    extern __shared__ float smem[];
    constexpr int ACH = 128 * ASTR, WCH = 96 * 32, STG = ACH + WCH;
    constexpr int KD = HIDDEN_DIM, NC = KD / 32, NSTG = 3;

    const int tid  = threadIdx.x;
    const int warp = tid >> 5, lane = tid & 31;
    const int gid  = lane >> 2, tig = lane & 3;
    const int wm   = (warp >> 1) * 32;
    const int wb   = warp & 1;
    const int wn   = wb * 48;
    const int m0   = blockIdx.x * 128;

    uint32_t smem_u = (uint32_t)__cvta_generic_to_shared(smem);
    const int crow = tid >> 3, cj = tid & 7, cc4 = cj << 2;

    auto issue = [&](int c) {
        int s = c % NSTG, kc = c * 32;
        uint32_t abuf = smem_u + (s * STG) * 4;
#pragma unroll
        for (int it = 0; it < 4; ++it) {
            int row = crow + it * 32;
            cp16(abuf + (row * ASTR + cc4) * 4, A + (size_t)(m0 + row) * KD + kc + cc4);
        }
        uint32_t wbuf = abuf + ACH * 4;
#pragma unroll
        for (int it = 0; it < 3; ++it) {
            int r = crow + it * 32;
            cp16(wbuf + (r * 32 + (((cj + r) & 7) << 2)) * 4,
                 W + (size_t)r * KD + kc + cc4);
        }
    };

    issue(0); cp_commit();
    issue(1); cp_commit();

    float4 acc[2][6];
#pragma unroll
    for (int i = 0; i < 2; ++i)
#pragma unroll
        for (int j = 0; j < 6; ++j) acc[i][j] = make_float4(0.f, 0.f, 0.f, 0.f);

    for (int c = 0; c < NC; ++c) {
        cp_wait<1>();                         // chunk c complete
        __syncthreads();                      // prev readers of stage (c+2)%3 done
        if (c + 2 < NC) issue(c + 2);
        cp_commit();

        const uint32_t* As = (const uint32_t*)(smem + (c % NSTG) * STG);
        const uint32_t* Ws = (const uint32_t*)(smem + (c % NSTG) * STG + ACH);

#pragma unroll
        for (int ks4 = 0; ks4 < 4; ++ks4) {
            const int k = ks4 * 8;
            uint32_t a[2][4];
#pragma unroll
            for (int mi = 0; mi < 2; ++mi) {
                int r = wm + mi * 16 + gid;
                a[mi][0] = As[r * ASTR + k + tig];
                a[mi][1] = As[(r + 8) * ASTR + k + tig];
                a[mi][2] = As[r * ASTR + k + tig + 4];
                a[mi][3] = As[(r + 8) * ASTR + k + tig + 4];
            }
            uint32_t b[6][2];
#pragma unroll
            for (int ni = 0; ni < 6; ++ni) {
                int n = wn + ni * 8 + gid;
                int ch0 = (2 * ks4 + gid) & 7;
                int ch1 = (2 * ks4 + 1 + gid) & 7;
                b[ni][0] = Ws[n * 32 + (ch0 << 2) + tig];
                b[ni][1] = Ws[n * 32 + (ch1 << 2) + tig];
            }
#pragma unroll
            for (int mi = 0; mi < 2; ++mi)
#pragma unroll
                for (int ni = 0; ni < 6; ++ni) mma_tf32(acc[mi][ni], a[mi], b[ni]);
        }
    }

#pragma unroll
    for (int mi = 0; mi < 2; ++mi) {
        int r0 = m0 + wm + mi * 16 + gid;
#pragma unroll
        for (int half = 0; half < 2; ++half) {
            int m = r0 + half * 8;
#pragma unroll
            for (int ni = 0; ni < 6; ++ni) {
                float v0 = half ? acc[mi][ni].z : acc[mi][ni].x;
                float v1 = half ? acc[mi][ni].w : acc[mi][ni].y;
#pragma unroll
                for (int e = 0; e < 2; ++e) {
                    int nl = wn + ni * 8 + tig * 2 + e;
                    float v = (e ? v1 : v0) + bias[nl];
                    out[(size_t)m * CDIM + nl] = res[(size_t)m * CDIM + nl] + v;
                }
            }
        }
    }
}

// ---------------------------------------------------------------------------
// Tensor-core attention (unchanged from R9/R11).
// ---------------------------------------------------------------------------
#define QSTR 28
#define PSTR 68

__global__ void __launch_bounds__(256) attn_mma(const float* __restrict__ qkv,
                                                float* __restrict__ attnout) {
    extern __shared__ float sm[];
    float* Qs = sm;
    float* Ks = Qs + 256 * QSTR;
    float* Vs = Ks + 256 * QSTR;
    float* Ps = Vs + 256 * 24;
    float* Ls = Ps + 256 * PSTR;
    unsigned char* grp = (unsigned char*)(Ls + 512);

    const int w = blockIdx.x, h = blockIdx.y;
    const int tid = threadIdx.x, warp = tid >> 5, lane = tid & 31;
    const int gid = lane >> 2, tig = lane & 3;
    const int wm = (warp >> 1) * 64;
    const int wb = warp & 1;
    const size_t hs = (size_t)NTOK * HD;
    const float* qb = qkv + (((size_t)0 * NWIN + w) * NHEADS + h) * hs;
    const float* kg = qkv + (((size_t)1 * NWIN + w) * NHEADS + h) * hs;
    const float* vg = qkv + (((size_t)2 * NWIN + w) * NHEADS + h) * hs;

#pragma unroll
    for (int it = 0; it < 6; ++it) {
        int idx = tid + it * 256;
        int row = idx / 6, c4 = (idx % 6) * 4;
        float4 q4 = *(const float4*)(qb + row * 24 + c4);
        float4 k4 = *(const float4*)(kg + row * 24 + c4);
        float4 v4 = *(const float4*)(vg + row * 24 + c4);
        Qs[row*QSTR+c4+0]=q4.x; Qs[row*QSTR+c4+1]=q4.y; Qs[row*QSTR+c4+2]=q4.z; Qs[row*QSTR+c4+3]=q4.w;
        Ks[row*QSTR+c4+0]=k4.x; Ks[row*QSTR+c4+1]=k4.y; Ks[row*QSTR+c4+2]=k4.z; Ks[row*QSTR+c4+3]=k4.w;
        *(float4*)(Vs + row * 24 + c4) = v4;
    }
    grp[tid] = (unsigned char)group_of(w & 255, tid);
    __syncthreads();

    const uint32_t* Qu = (const uint32_t*)Qs;
    const uint32_t* Ku = (const uint32_t*)Ks;
    const uint32_t* Vu = (const uint32_t*)Vs;
    const uint32_t* Pu = (const uint32_t*)Ps;

    float4 oacc[4][3];
#pragma unroll
    for (int i = 0; i < 4; ++i)
#pragma unroll
        for (int j = 0; j < 3; ++j) oacc[i][j] = make_float4(0.f, 0.f, 0.f, 0.f);
    float rs[4][2];
#pragma unroll
    for (int i = 0; i < 4; ++i) { rs[i][0] = 0.f; rs[i][1] = 0.f; }

    for (int kb = 0; kb < 4; ++kb) {
        float4 sacc[4][4];
#pragma unroll
        for (int i = 0; i < 4; ++i)
#pragma unroll
            for (int j = 0; j < 4; ++j) sacc[i][j] = make_float4(0.f, 0.f, 0.f, 0.f);

#pragma unroll
        for (int kk = 0; kk < 3; ++kk) {
            const int k8 = kk * 8;
            uint32_t a[4][4], b[4][2];
#pragma unroll
            for (int mi = 0; mi < 4; ++mi) {
                int r = wm + mi * 16 + gid;
                a[mi][0] = Qu[r * QSTR + k8 + tig];
                a[mi][1] = Qu[(r + 8) * QSTR + k8 + tig];
                a[mi][2] = Qu[r * QSTR + k8 + tig + 4];
                a[mi][3] = Qu[(r + 8) * QSTR + k8 + tig + 4];
            }
#pragma unroll
            for (int ni = 0; ni < 4; ++ni) {
                int n = kb * 64 + wb * 32 + ni * 8 + gid;
                b[ni][0] = Ku[n * QSTR + k8 + tig];
                b[ni][1] = Ku[n * QSTR + k8 + tig + 4];
            }
#pragma unroll
            for (int mi = 0; mi < 4; ++mi)
#pragma unroll
                for (int ni = 0; ni < 4; ++ni) mma_tf32(sacc[mi][ni], a[mi], b[ni]);
        }

#pragma unroll
        for (int mi = 0; mi < 4; ++mi) {
            int r0 = wm + mi * 16 + gid;
            int rg0 = grp[r0], rg1 = grp[r0 + 8];
#pragma unroll
            for (int ni = 0; ni < 4; ++ni) {
                int cc = kb * 64 + wb * 32 + ni * 8 + 2 * tig;
                int cg0 = grp[cc], cg1 = grp[cc + 1];
                float4 s = sacc[mi][ni];
                float p00 = __expf(s.x + (cg0 == rg0 ? 0.f : -100.f));
                float p01 = __expf(s.y + (cg1 == rg0 ? 0.f : -100.f));
                float p10 = __expf(s.z + (cg0 == rg1 ? 0.f : -100.f));
                float p11 = __expf(s.w + (cg1 == rg1 ? 0.f : -100.f));
                rs[mi][0] += p00 + p01;
                rs[mi][1] += p10 + p11;
                int pc = wb * 32 + ni * 8 + 2 * tig;
                *(float2*)(Ps + r0 * PSTR + pc)       = make_float2(p00, p01);
                *(float2*)(Ps + (r0 + 8) * PSTR + pc) = make_float2(p10, p11);
            }
        }
        __syncwarp();

#pragma unroll
        for (int kk = 0; kk < 4; ++kk) {
            const int kp = wb * 32 + kk * 8;
            const int kv = kb * 64 + kp;
            uint32_t a[4][4], b[3][2];
#pragma unroll
            for (int mi = 0; mi < 4; ++mi) {
                int r = wm + mi * 16 + gid;
                a[mi][0] = Pu[r * PSTR + kp + tig];
                a[mi][1] = Pu[(r + 8) * PSTR + kp + tig];
                a[mi][2] = Pu[r * PSTR + kp + tig + 4];
                a[mi][3] = Pu[(r + 8) * PSTR + kp + tig + 4];
            }
#pragma unroll
            for (int nd = 0; nd < 3; ++nd) {
                int n = nd * 8 + gid;
                b[nd][0] = Vu[(kv + tig) * 24 + n];
                b[nd][1] = Vu[(kv + tig + 4) * 24 + n];
            }
#pragma unroll
            for (int mi = 0; mi < 4; ++mi)
#pragma unroll
                for (int nd = 0; nd < 3; ++nd) mma_tf32(oacc[mi][nd], a[mi], b[nd]);
        }
        __syncwarp();
    }

#pragma unroll
    for (int mi = 0; mi < 4; ++mi)
#pragma unroll
        for (int hf = 0; hf < 2; ++hf) {
            float v = rs[mi][hf];
            v += __shfl_xor_sync(0xffffffffu, v, 1);
            v += __shfl_xor_sync(0xffffffffu, v, 2);
            rs[mi][hf] = v;
        }
    if (tig == 0) {
#pragma unroll
        for (int mi = 0; mi < 4; ++mi) {
            Ls[wb * 256 + wm + mi * 16 + gid]     = rs[mi][0];
            Ls[wb * 256 + wm + mi * 16 + gid + 8] = rs[mi][1];
        }
    }
    __syncthreads();

    float* OS = Qs;
    const int OSTR = 26;
    if (wb == 1) {
#pragma unroll
        for (int mi = 0; mi < 4; ++mi) {
            int r0 = wm + mi * 16 + gid;
#pragma unroll
            for (int nd = 0; nd < 3; ++nd) {
                int c = nd * 8 + 2 * tig;
                *(float2*)(OS + r0 * OSTR + c)       = make_float2(oacc[mi][nd].x, oacc[mi][nd].y);
                *(float2*)(OS + (r0 + 8) * OSTR + c) = make_float2(oacc[mi][nd].z, oacc[mi][nd].w);
            }
        }
    }
    __syncthreads();
    if (wb == 0) {
#pragma unroll
        for (int mi = 0; mi < 4; ++mi) {
            int r0 = wm + mi * 16 + gid, r1 = r0 + 8;
            float inv0 = 1.f / (Ls[r0] + Ls[256 + r0]);
            float inv1 = 1.f / (Ls[r1] + Ls[256 + r1]);
#pragma unroll
            for (int nd = 0; nd < 3; ++nd) {
                int c = nd * 8 + 2 * tig;
                float2 t0 = *(float2*)(OS + r0 * OSTR + c);
                float2 t1 = *(float2*)(OS + r1 * OSTR + c);
                float* o0 = attnout + ((size_t)w * NTOK + r0) * CDIM + h * HD + c;
                float* o1 = attnout + ((size_t)w * NTOK + r1) * CDIM + h * HD + c;
                o0[0] = (oacc[mi][nd].x + t0.x) * inv0;
                o0[1] = (oacc[mi][nd].y + t0.y) * inv0;
                o1[0] = (oacc[mi][nd].z + t1.x) * inv1;
                o1[1] = (oacc[mi][nd].w + t1.y) * inv1;
            }
        }
    }
}

// ---------------------------------------------------------------------------
extern "C" void kernel_launch(void* const* d_in, const int* in_sizes, int n_in,
                              void* d_out, int out_size) {
    (void)in_sizes; (void)n_in; (void)out_size;
    const float* x       = (const float*)d_in[0];
    const float* norm1_g = (const float*)d_in[2];
    const float* norm1_b = (const float*)d_in[3];
    const float* qkv_w   = (const float*)d_in[4];
    const float* qkv_b   = (const float*)d_in[5];
    const float* proj_w  = (const float*)d_in[6];
    const float* proj_b  = (const float*)d_in[7];
    const float* norm2_g = (const float*)d_in[8];
    const float* norm2_b = (const float*)d_in[9];
    const float* fc1_w   = (const float*)d_in[10];
    const float* fc1_b   = (const float*)d_in[11];
    const float* fc2_w   = (const float*)d_in[12];
    const float* fc2_b   = (const float*)d_in[13];
    float* out = (float*)d_out;

    float *qkv, *attn, *x2, *hbuf;
    cudaGetSymbolAddress((void**)&qkv,  g_qkv);
    cudaGetSymbolAddress((void**)&attn, g_attn);
    cudaGetSymbolAddress((void**)&x2,   g_x2);
    cudaGetSymbolAddress((void**)&hbuf, g_h);

    const int fz_smem  = (128 * ASTR2 + 3 * 96 * 32) * 4;   // 88064 B
    const int fc2_smem = 3 * (128 * ASTR + 96 * 32) * 4;    // 92160 B
    cudaFuncSetAttribute(gemm_fz<EPI_QKV,  true,  true,  3>, cudaFuncAttributeMaxDynamicSharedMemorySize, fz_smem);
    cudaFuncSetAttribute(gemm_fz<EPI_PROJ, false, false, 1>, cudaFuncAttributeMaxDynamicSharedMemorySize, fz_smem);
    cudaFuncSetAttribute(gemm_fz<EPI_FC1,  true,  false, 4>, cudaFuncAttributeMaxDynamicSharedMemorySize, fz_smem);
    cudaFuncSetAttribute(gemm_fc2, cudaFuncAttributeMaxDynamicSharedMemorySize, fc2_smem);

    const int attn_smem = (256 * QSTR * 2 + 256 * 24 + 256 * PSTR + 512 + 64) * 4;
    cudaFuncSetAttribute(attn_mma, cudaFuncAttributeMaxDynamicSharedMemorySize, attn_smem);

    gemm_fz<EPI_QKV, true, true, 3><<<1024, 256, fz_smem>>>(
        x, qkv_w, qkv_b, nullptr, norm1_g, norm1_b, qkv);
    attn_mma<<<dim3(NWIN, NHEADS), 256, attn_smem>>>(qkv, attn);
    gemm_fz<EPI_PROJ, false, false, 1><<<1024, 256, fz_smem>>>(
        attn, proj_w, proj_b, x, nullptr, nullptr, x2);
    gemm_fz<EPI_FC1, true, false, 4><<<1024, 256, fz_smem>>>(
        x2, fc1_w, fc1_b, nullptr, norm2_g, norm2_b, hbuf);
    gemm_fc2<<<1024, 256, fc2_smem>>>(hbuf, fc2_w, fc2_b, x2, out);
}

// round 14
// speedup vs baseline: 1.4107x; 1.2372x over previous
#include <cuda_runtime.h>
#include <cuda_bf16.h>
#include <cstdint>
#include <cstddef>

#define TOKENS   131072
#define CDIM     96
#define NWIN     512
#define NTOK     256
#define HD       24
#define NHEADS   4
#define HIDDEN_DIM 384

typedef unsigned long long ull;

// Scratch (device globals; float4 for 16B alignment of cp.async/uint4 access)
__device__ float4 g_qkv16b [4718592];   // 3*T*C bf16
__device__ float4 g_attn16b[1572864];   // T*C bf16
__device__ float4 g_h16b   [6291456];   // T*HIDDEN bf16
__device__ float4 g_x2b    [3145728];   // T*C fp32 (residual trunk)
__device__ float4 g_wbb    [13824];     // 110592 bf16 weights: qkv|proj|fc1|fc2

#define WOFF_QKV 0
#define WOFF_PROJ 27648
#define WOFF_FC1 36864
#define WOFF_FC2 73728

__device__ __forceinline__ int nat_index(int t) {
    int r = t & 255, w = t >> 8;
    int b = w >> 8, wi = w & 255;
    int d  = ((((wi >> 6) & 3) << 2) | ((r >> 6) & 3));
    int hh = ((((wi >> 4) & 3) << 2) | ((r >> 4) & 3));
    int ww = ((((wi >> 2) & 3) << 2) | ((r >> 2) & 3));
    int tt = (((wi & 3) << 2) | (r & 3));
    d = (d + 2) & 15; hh = (hh + 2) & 15; ww = (ww + 2) & 15; tt = (tt + 2) & 15;
    return (((b * 16 + d) * 16 + hh) * 16 + ww) * 16 + tt;
}

__device__ __forceinline__ int group_of(int wi, int r) {
    int g = 0;
#pragma unroll
    for (int a = 3; a >= 0; --a) {
        int c = ((((wi >> (2 * a)) & 3) << 2) | ((r >> (2 * a)) & 3));
        int s = (c < 12) ? 0 : ((c < 14) ? 1 : 2);
        g = g * 3 + s;
    }
    return g;
}

__device__ __forceinline__ void mma_tf32(float4& d, const uint32_t a[4], const uint32_t b[2]) {
    asm("mma.sync.aligned.m16n8k8.row.col.f32.tf32.tf32.f32 "
        "{%0,%1,%2,%3},{%4,%5,%6,%7},{%8,%9},{%0,%1,%2,%3};"
        : "+f"(d.x), "+f"(d.y), "+f"(d.z), "+f"(d.w)
        : "r"(a[0]), "r"(a[1]), "r"(a[2]), "r"(a[3]), "r"(b[0]), "r"(b[1]));
}

__device__ __forceinline__ void mma_bf16(float4& d, const uint32_t a[4], const uint32_t b[2]) {
    asm("mma.sync.aligned.m16n8k16.row.col.f32.bf16.bf16.f32 "
        "{%0,%1,%2,%3},{%4,%5,%6,%7},{%8,%9},{%0,%1,%2,%3};"
        : "+f"(d.x), "+f"(d.y), "+f"(d.z), "+f"(d.w)
        : "r"(a[0]), "r"(a[1]), "r"(a[2]), "r"(a[3]), "r"(b[0]), "r"(b[1]));
}

// cp.async helpers
__device__ __forceinline__ void cp16(uint32_t dst, const void* src) {
    asm volatile("cp.async.cg.shared.global [%0],[%1],16;" :: "r"(dst), "l"(src));
}
__device__ __forceinline__ void cp_commit() { asm volatile("cp.async.commit_group;"); }
template <int N>
__device__ __forceinline__ void cp_wait() { asm volatile("cp.async.wait_group %0;" :: "n"(N)); }

__device__ __forceinline__ uint32_t bf2u(float a, float b) {
    __nv_bfloat162 t = __floats2bfloat162_rn(a, b);
    return *(uint32_t*)&t;
}

// Fast exact-enough GELU: erf via Abramowitz-Stegun 7.1.26 (|err| <= 1.5e-7).
__device__ __forceinline__ float gelu_f(float v) {
    float z = fabsf(v) * 0.70710678118654752f;
    float t = __frcp_rn(fmaf(0.3275911f, z, 1.f));
    float p = fmaf(fmaf(fmaf(fmaf(1.061405429f, t, -1.453152027f), t, 1.421413741f),
                        t, -0.284496736f), t, 0.254829592f) * t;
    float e = __expf(-z * z);
    float er = copysignf(fmaf(-p, e, 1.f), v);
    return 0.5f * v * (1.f + er);
}

enum { EPI_QKV = 0, EPI_PROJ = 1, EPI_FC1 = 2 };

// ---------------------------------------------------------------------------
// Weight fp32->bf16 conversion (one small launch per call).
// ---------------------------------------------------------------------------
__global__ void cvt_w(const float* __restrict__ qw, const float* __restrict__ pw,
                      const float* __restrict__ f1, const float* __restrict__ f2) {
    int i = blockIdx.x * 256 + threadIdx.x;     // handles 2 elems
    if (i >= 55296) return;
    int e = i * 2;
    const float* src; int off;
    if (e < WOFF_PROJ)      { src = qw; off = e; }
    else if (e < WOFF_FC1)  { src = pw; off = e - WOFF_PROJ; }
    else if (e < WOFF_FC2)  { src = f1; off = e - WOFF_FC1; }
    else                    { src = f2; off = e - WOFF_FC2; }
    float2 v = *(const float2*)(src + off);
    ((uint32_t*)g_wbb)[i] = bf2u(v.x, v.y);
}

// ---------------------------------------------------------------------------
// bf16 GEMM (K=96): A resident in smem as bf16 [128][52w] (48 data words);
// W streamed in 3-stage ring of [96][20w] chunks (K=32 each).  LNF: A staged
// fp32 into Fs[128][100], LayerNorm'ed + converted to bf16 Ab.  Single sync
// per chunk (R13 scheme).  Conflict-free frags: 52*gid, 20*gid ≡ 4k mod 32.
// ---------------------------------------------------------------------------
#define AW   52
#define WRW  20
#define WCW  (96 * WRW)
#define FSW  100

template <int E, bool LNF, bool GATHER, int NB>
__global__ void __launch_bounds__(256, 2) gemm_bf(const void* __restrict__ Ain,
                                                  const __nv_bfloat16* __restrict__ W,
                                                  const float* __restrict__ bias,
                                                  const float* __restrict__ res,
                                                  const float* __restrict__ gamma,
                                                  const float* __restrict__ beta,
                                                  void* __restrict__ outv) {
    extern __shared__ uint32_t sw[];
    uint32_t* Ab   = sw;                  // [128][52]
    uint32_t* ring = sw + 128 * AW;       // 3 * WCW
    float*    Fs   = (float*)(sw + 128 * AW + 3 * WCW);
    constexpr int NC = NB * 3;

    const int tid  = threadIdx.x;
    const int warp = tid >> 5, lane = tid & 31;
    const int gid  = lane >> 2, tig = lane & 3;
    const int wm   = (warp >> 1) * 32;
    const int wb   = warp & 1;
    const int wn   = wb * 48;
    const int m0   = blockIdx.x * 128;

    uint32_t ab_u   = (uint32_t)__cvta_generic_to_shared(Ab);
    uint32_t ring_u = (uint32_t)__cvta_generic_to_shared(ring);
    uint32_t fs_u   = (uint32_t)__cvta_generic_to_shared(Fs);

    // ---- group 0: A ----
    if (LNF) {
        const float* Afp = (const float*)Ain;
#pragma unroll
        for (int it = 0; it < 12; ++it) {
            int idx = tid + it * 256;
            int row = idx / 24, c4 = (idx % 24) << 2;
            int m = m0 + row;
            cp16(fs_u + (row * FSW + c4) * 4,
                 Afp + (size_t)(GATHER ? nat_index(m) : m) * CDIM + c4);
        }
    } else {
        const __nv_bfloat16* Abf = (const __nv_bfloat16*)Ain;
#pragma unroll
        for (int it = 0; it < 6; ++it) {
            int idx = tid + it * 256;
            int row = idx / 12, ch = idx % 12;
            cp16(ab_u + (row * AW + ch * 4) * 4,
                 Abf + (size_t)(m0 + row) * CDIM + ch * 8);
        }
    }
    cp_commit();

    auto issueW = [&](int c) {
        int st = c % 3, n0 = (c / 3) * 96, kc = (c % 3) * 32;
        uint32_t wbuf = ring_u + (st * WCW) * 4;
#pragma unroll
        for (int it = 0; it < 2; ++it) {
            int idx = tid + it * 256;
            if (idx < 384) {
                int row = idx >> 2, ch = idx & 3;
                cp16(wbuf + (row * WRW + ch * 4) * 4,
                     W + (size_t)(n0 + row) * CDIM + kc + ch * 8);
            }
        }
    };
    issueW(0); cp_commit();
    issueW(1); cp_commit();

    if (LNF) {
        cp_wait<2>();                       // A complete
        __syncthreads();
        int row = tid >> 1, half = tid & 1;
        float s = 0.f, sq = 0.f;
#pragma unroll
        for (int i = 0; i < 48; ++i) {
            float v = Fs[row * FSW + half * 48 + i];
            s += v; sq += v * v;
        }
        s  += __shfl_xor_sync(0xffffffffu, s, 1);
        sq += __shfl_xor_sync(0xffffffffu, sq, 1);
        float mean = s * (1.f / 96.f);
        float var  = sq * (1.f / 96.f) - mean * mean;
        float rstd = rsqrtf(var + 1e-5f);
#pragma unroll
        for (int i = 0; i < 24; ++i) {
            int c0 = half * 48 + 2 * i;
            float v0 = (Fs[row * FSW + c0]     - mean) * rstd * __ldg(gamma + c0)     + __ldg(beta + c0);
            float v1 = (Fs[row * FSW + c0 + 1] - mean) * rstd * __ldg(gamma + c0 + 1) + __ldg(beta + c0 + 1);
            Ab[row * AW + half * 24 + i] = bf2u(v0, v1);
        }
        // first loop-top __syncthreads publishes Ab
    }

    float4 acc[2][6];
#pragma unroll
    for (int i = 0; i < 2; ++i)
#pragma unroll
        for (int j = 0; j < 6; ++j) acc[i][j] = make_float4(0.f, 0.f, 0.f, 0.f);

    for (int c = 0; c < NC; ++c) {
        cp_wait<1>();
        __syncthreads();
        if (c + 2 < NC) issueW(c + 2);
        cp_commit();

        const uint32_t* Ws = ring + (c % 3) * WCW;
        const int kwb = (c % 3) * 16;       // word offset into A rows

#pragma unroll
        for (int ks = 0; ks < 2; ++ks) {    // two K=16 steps
            const int kw = kwb + ks * 8;
            const int wk = ks * 8;
            uint32_t a[2][4];
#pragma unroll
            for (int mi = 0; mi < 2; ++mi) {
                int r = wm + mi * 16 + gid;
                a[mi][0] = Ab[r * AW + kw + tig];
                a[mi][1] = Ab[(r + 8) * AW + kw + tig];
                a[mi][2] = Ab[r * AW + kw + tig + 4];
                a[mi][3] = Ab[(r + 8) * AW + kw + tig + 4];
            }
            uint32_t b[6][2];
#pragma unroll
            for (int ni = 0; ni < 6; ++ni) {
                int n = wn + ni * 8 + gid;
                b[ni][0] = Ws[n * WRW + wk + tig];
                b[ni][1] = Ws[n * WRW + wk + tig + 4];
            }
#pragma unroll
            for (int mi = 0; mi < 2; ++mi)
#pragma unroll
                for (int ni = 0; ni < 6; ++ni) mma_bf16(acc[mi][ni], a[mi], b[ni]);
        }

        if ((c % 3) == 2) {
            const int nb = c / 3, n0 = nb * 96;
#pragma unroll
            for (int mi = 0; mi < 2; ++mi) {
                int r0 = m0 + wm + mi * 16 + gid;
#pragma unroll
                for (int half = 0; half < 2; ++half) {
                    int m = r0 + half * 8;
                    size_t proj_dst = 0;
                    if (E == EPI_PROJ) proj_dst = (size_t)nat_index(m) * CDIM;
                    int w = m >> 8, rr = m & 255;
#pragma unroll
                    for (int ni = 0; ni < 6; ++ni) {
                        float v0 = half ? acc[mi][ni].z : acc[mi][ni].x;
                        float v1 = half ? acc[mi][ni].w : acc[mi][ni].y;
                        int nl = wn + ni * 8 + tig * 2;          // even
                        v0 += bias[n0 + nl];
                        v1 += bias[n0 + nl + 1];
                        if (E == EPI_QKV) {
                            const float sc = (nb == 0) ? 0.20412414523193154f : 1.0f;
                            int hh = nl / 24, dd = nl % 24;
                            __nv_bfloat16* ob = (__nv_bfloat16*)outv;
                            *(uint32_t*)(ob + (((size_t)nb * NWIN + w) * NHEADS + hh) * (NTOK * HD) + rr * HD + dd)
                                = bf2u(v0 * sc, v1 * sc);
                        } else if (E == EPI_PROJ) {
                            float* of = (float*)outv;
                            of[proj_dst + nl]     = res[proj_dst + nl]     + v0;
                            of[proj_dst + nl + 1] = res[proj_dst + nl + 1] + v1;
                        } else {  // EPI_FC1
                            __nv_bfloat16* ob = (__nv_bfloat16*)outv;
                            *(uint32_t*)(ob + (size_t)m * HIDDEN_DIM + n0 + nl)
                                = bf2u(gelu_f(v0), gelu_f(v1));
                        }
                    }
                }
            }
            if (c + 1 < NC) {
#pragma unroll
                for (int i = 0; i < 2; ++i)
#pragma unroll
                    for (int j = 0; j < 6; ++j) acc[i][j] = make_float4(0.f, 0.f, 0.f, 0.f);
            }
        }
    }
}

// ---------------------------------------------------------------------------
// bf16 streaming GEMM for fc2 (K=384): A+W chunks [128][20w]+[96][20w],
// 3-stage ring, single sync per chunk.  Output fp32 + residual.
// ---------------------------------------------------------------------------
__global__ void __launch_bounds__(256, 2) gemm_fc2b(const __nv_bfloat16* __restrict__ A,
                                                    const __nv_bfloat16* __restrict__ W,
                                                    const float* __restrict__ bias,
                                                    const float* __restrict__ res,
                                                    float* __restrict__ out) {
    extern __shared__ uint32_t sw[];
    constexpr int ACHW = 128 * WRW, WCHW = 96 * WRW, STG = ACHW + WCHW;
    constexpr int KD = HIDDEN_DIM, NC = KD / 32;

    const int tid  = threadIdx.x;
    const int warp = tid >> 5, lane = tid & 31;
    const int gid  = lane >> 2, tig = lane & 3;
    const int wm   = (warp >> 1) * 32;
    const int wb   = warp & 1;
    const int wn   = wb * 48;
    const int m0   = blockIdx.x * 128;

    uint32_t sw_u = (uint32_t)__cvta_generic_to_shared(sw);

    auto issue = [&](int c) {
        int st = c % 3, kc = c * 32;
        uint32_t abuf = sw_u + (st * STG) * 4;
#pragma unroll
        for (int it = 0; it < 2; ++it) {
            int idx = tid + it * 256;
            int row = idx >> 2, ch = idx & 3;
            cp16(abuf + (row * WRW + ch * 4) * 4,
                 A + (size_t)(m0 + row) * KD + kc + ch * 8);
        }
        uint32_t wbuf = abuf + ACHW * 4;
#pragma unroll
        for (int it = 0; it < 2; ++it) {
            int idx = tid + it * 256;
            if (idx < 384) {
                int row = idx >> 2, ch = idx & 3;
                cp16(wbuf + (row * WRW + ch * 4) * 4,
                     W + (size_t)row * KD + kc + ch * 8);
            }
        }
    };

    issue(0); cp_commit();
    issue(1); cp_commit();

    float4 acc[2][6];
#pragma unroll
    for (int i = 0; i < 2; ++i)
#pragma unroll
        for (int j = 0; j < 6; ++j) acc[i][j] = make_float4(0.f, 0.f, 0.f, 0.f);

    for (int c = 0; c < NC; ++c) {
        cp_wait<1>();
        __syncthreads();
        if (c + 2 < NC) issue(c + 2);
        cp_commit();

        const uint32_t* As = sw + (c % 3) * STG;
        const uint32_t* Ws = sw + (c % 3) * STG + ACHW;

#pragma unroll
        for (int ks = 0; ks < 2; ++ks) {
            const int kw = ks * 8;
            uint32_t a[2][4];
#pragma unroll
            for (int mi = 0; mi < 2; ++mi) {
                int r = wm + mi * 16 + gid;
                a[mi][0] = As[r * WRW + kw + tig];
                a[mi][1] = As[(r + 8) * WRW + kw + tig];
                a[mi][2] = As[r * WRW + kw + tig + 4];
                a[mi][3] = As[(r + 8) * WRW + kw + tig + 4];
            }
            uint32_t b[6][2];
#pragma unroll
            for (int ni = 0; ni < 6; ++ni) {
                int n = wn + ni * 8 + gid;
                b[ni][0] = Ws[n * WRW + kw + tig];
                b[ni][1] = Ws[n * WRW + kw + tig + 4];
            }
#pragma unroll
            for (int mi = 0; mi < 2; ++mi)
#pragma unroll
                for (int ni = 0; ni < 6; ++ni) mma_bf16(acc[mi][ni], a[mi], b[ni]);
        }
    }

#pragma unroll
    for (int mi = 0; mi < 2; ++mi) {
        int r0 = m0 + wm + mi * 16 + gid;
#pragma unroll
        for (int half = 0; half < 2; ++half) {
            int m = r0 + half * 8;
#pragma unroll
            for (int ni = 0; ni < 6; ++ni) {
                float v0 = half ? acc[mi][ni].z : acc[mi][ni].x;
                float v1 = half ? acc[mi][ni].w : acc[mi][ni].y;
                int nl = wn + ni * 8 + tig * 2;
                out[(size_t)m * CDIM + nl]     = res[(size_t)m * CDIM + nl]     + v0 + bias[nl];
                out[(size_t)m * CDIM + nl + 1] = res[(size_t)m * CDIM + nl + 1] + v1 + bias[nl + 1];
            }
        }
    }
}

// ---------------------------------------------------------------------------
// Tensor-core attention (tf32 internals unchanged; bf16 in/out).
// ---------------------------------------------------------------------------
#define QSTR 28
#define PSTR 68

__global__ void __launch_bounds__(256) attn_mma(const __nv_bfloat16* __restrict__ qkv,
                                                __nv_bfloat16* __restrict__ attnout) {
    extern __shared__ float sm[];
    float* Qs = sm;
    float* Ks = Qs + 256 * QSTR;
    float* Vs = Ks + 256 * QSTR;
    float* Ps = Vs + 256 * 24;
    float* Ls = Ps + 256 * PSTR;
    unsigned char* grp = (unsigned char*)(Ls + 512);

    const int w = blockIdx.x, h = blockIdx.y;
    const int tid = threadIdx.x, warp = tid >> 5, lane = tid & 31;
    const int gid = lane >> 2, tig = lane & 3;
    const int wm = (warp >> 1) * 64;
    const int wb = warp & 1;
    const size_t hs = (size_t)NTOK * HD;
    const __nv_bfloat16* qb = qkv + (((size_t)0 * NWIN + w) * NHEADS + h) * hs;
    const __nv_bfloat16* kg = qkv + (((size_t)1 * NWIN + w) * NHEADS + h) * hs;
    const __nv_bfloat16* vg = qkv + (((size_t)2 * NWIN + w) * NHEADS + h) * hs;

#pragma unroll
    for (int it = 0; it < 3; ++it) {
        int idx = tid + it * 256;           // 768: row 0..255, seg 0..2 (8 elems)
        int row = idx / 3, seg = idx % 3;
        uint4 qv = *(const uint4*)(qb + row * 24 + seg * 8);
        uint4 kv = *(const uint4*)(kg + row * 24 + seg * 8);
        uint4 vv = *(const uint4*)(vg + row * 24 + seg * 8);
        const __nv_bfloat162* q2 = (const __nv_bfloat162*)&qv;
        const __nv_bfloat162* k2 = (const __nv_bfloat162*)&kv;
        const __nv_bfloat162* v2 = (const __nv_bfloat162*)&vv;
#pragma unroll
        for (int j = 0; j < 4; ++j) {
            float2 qf = __bfloat1622float2(q2[j]);
            float2 kf = __bfloat1622float2(k2[j]);
            float2 vf = __bfloat1622float2(v2[j]);
            Qs[row * QSTR + seg * 8 + 2 * j]     = qf.x;
            Qs[row * QSTR + seg * 8 + 2 * j + 1] = qf.y;
            Ks[row * QSTR + seg * 8 + 2 * j]     = kf.x;
            Ks[row * QSTR + seg * 8 + 2 * j + 1] = kf.y;
            Vs[row * 24 + seg * 8 + 2 * j]       = vf.x;
            Vs[row * 24 + seg * 8 + 2 * j + 1]   = vf.y;
        }
    }
    grp[tid] = (unsigned char)group_of(w & 255, tid);
    __syncthreads();

    const uint32_t* Qu = (const uint32_t*)Qs;
    const uint32_t* Ku = (const uint32_t*)Ks;
    const uint32_t* Vu = (const uint32_t*)Vs;
    const uint32_t* Pu = (const uint32_t*)Ps;

    float4 oacc[4][3];
#pragma unroll
    for (int i = 0; i < 4; ++i)
#pragma unroll
        for (int j = 0; j < 3; ++j) oacc[i][j] = make_float4(0.f, 0.f, 0.f, 0.f);
    float rs[4][2];
#pragma unroll
    for (int i = 0; i < 4; ++i) { rs[i][0] = 0.f; rs[i][1] = 0.f; }

    for (int kb = 0; kb < 4; ++kb) {
        float4 sacc[4][4];
#pragma unroll
        for (int i = 0; i < 4; ++i)
#pragma unroll
            for (int j = 0; j < 4; ++j) sacc[i][j] = make_float4(0.f, 0.f, 0.f, 0.f);

#pragma unroll
        for (int kk = 0; kk < 3; ++kk) {
            const int k8 = kk * 8;
            uint32_t a[4][4], b[4][2];
#pragma unroll
            for (int mi = 0; mi < 4; ++mi) {
                int r = wm + mi * 16 + gid;
                a[mi][0] = Qu[r * QSTR + k8 + tig];
                a[mi][1] = Qu[(r + 8) * QSTR + k8 + tig];
                a[mi][2] = Qu[r * QSTR + k8 + tig + 4];
                a[mi][3] = Qu[(r + 8) * QSTR + k8 + tig + 4];
            }
#pragma unroll
            for (int ni = 0; ni < 4; ++ni) {
                int n = kb * 64 + wb * 32 + ni * 8 + gid;
                b[ni][0] = Ku[n * QSTR + k8 + tig];
                b[ni][1] = Ku[n * QSTR + k8 + tig + 4];
            }
#pragma unroll
            for (int mi = 0; mi < 4; ++mi)
#pragma unroll
                for (int ni = 0; ni < 4; ++ni) mma_tf32(sacc[mi][ni], a[mi], b[ni]);
        }

#pragma unroll
        for (int mi = 0; mi < 4; ++mi) {
            int r0 = wm + mi * 16 + gid;
            int rg0 = grp[r0], rg1 = grp[r0 + 8];
#pragma unroll
            for (int ni = 0; ni < 4; ++ni) {
                int cc = kb * 64 + wb * 32 + ni * 8 + 2 * tig;
                int cg0 = grp[cc], cg1 = grp[cc + 1];
                float4 s = sacc[mi][ni];
                float p00 = __expf(s.x + (cg0 == rg0 ? 0.f : -100.f));
                float p01 = __expf(s.y + (cg1 == rg0 ? 0.f : -100.f));
                float p10 = __expf(s.z + (cg0 == rg1 ? 0.f : -100.f));
                float p11 = __expf(s.w + (cg1 == rg1 ? 0.f : -100.f));
                rs[mi][0] += p00 + p01;
                rs[mi][1] += p10 + p11;
                int pc = wb * 32 + ni * 8 + 2 * tig;
                *(float2*)(Ps + r0 * PSTR + pc)       = make_float2(p00, p01);
                *(float2*)(Ps + (r0 + 8) * PSTR + pc) = make_float2(p10, p11);
            }
        }
        __syncwarp();

#pragma unroll
        for (int kk = 0; kk < 4; ++kk) {
            const int kp = wb * 32 + kk * 8;
            const int kv = kb * 64 + kp;
            uint32_t a[4][4], b[3][2];
#pragma unroll
            for (int mi = 0; mi < 4; ++mi) {
                int r = wm + mi * 16 + gid;
                a[mi][0] = Pu[r * PSTR + kp + tig];
                a[mi][1] = Pu[(r + 8) * PSTR + kp + tig];
                a[mi][2] = Pu[r * PSTR + kp + tig + 4];
                a[mi][3] = Pu[(r + 8) * PSTR + kp + tig + 4];
            }
#pragma unroll
            for (int nd = 0; nd < 3; ++nd) {
                int n = nd * 8 + gid;
                b[nd][0] = Vu[(kv + tig) * 24 + n];
                b[nd][1] = Vu[(kv + tig + 4) * 24 + n];
            }
#pragma unroll
            for (int mi = 0; mi < 4; ++mi)
#pragma unroll
                for (int nd = 0; nd < 3; ++nd) mma_tf32(oacc[mi][nd], a[mi], b[nd]);
        }
        __syncwarp();
    }

#pragma unroll
    for (int mi = 0; mi < 4; ++mi)
#pragma unroll
        for (int hf = 0; hf < 2; ++hf) {
            float v = rs[mi][hf];
            v += __shfl_xor_sync(0xffffffffu, v, 1);
            v += __shfl_xor_sync(0xffffffffu, v, 2);
            rs[mi][hf] = v;
        }
    if (tig == 0) {
#pragma unroll
        for (int mi = 0; mi < 4; ++mi) {
            Ls[wb * 256 + wm + mi * 16 + gid]     = rs[mi][0];
            Ls[wb * 256 + wm + mi * 16 + gid + 8] = rs[mi][1];
        }
    }
    __syncthreads();

    float* OS = Qs;
    const int OSTR = 26;
    if (wb == 1) {
#pragma unroll
        for (int mi = 0; mi < 4; ++mi) {
            int r0 = wm + mi * 16 + gid;
#pragma unroll
            for (int nd = 0; nd < 3; ++nd) {
                int c = nd * 8 + 2 * tig;
                *(float2*)(OS + r0 * OSTR + c)       = make_float2(oacc[mi][nd].x, oacc[mi][nd].y);
                *(float2*)(OS + (r0 + 8) * OSTR + c) = make_float2(oacc[mi][nd].z, oacc[mi][nd].w);
            }
        }
    }
    __syncthreads();
    if (wb == 0) {
#pragma unroll
        for (int mi = 0; mi < 4; ++mi) {
            int r0 = wm + mi * 16 + gid, r1 = r0 + 8;
            float inv0 = 1.f / (Ls[r0] + Ls[256 + r0]);
            float inv1 = 1.f / (Ls[r1] + Ls[256 + r1]);
#pragma unroll
            for (int nd = 0; nd < 3; ++nd) {
                int c = nd * 8 + 2 * tig;
                float2 t0 = *(float2*)(OS + r0 * OSTR + c);
                float2 t1 = *(float2*)(OS + r1 * OSTR + c);
                *(uint32_t*)(attnout + ((size_t)w * NTOK + r0) * CDIM + h * HD + c)
                    = bf2u((oacc[mi][nd].x + t0.x) * inv0, (oacc[mi][nd].y + t0.y) * inv0);
                *(uint32_t*)(attnout + ((size_t)w * NTOK + r1) * CDIM + h * HD + c)
                    = bf2u((oacc[mi][nd].z + t1.x) * inv1, (oacc[mi][nd].w + t1.y) * inv1);
            }
        }
    }
}

// ---------------------------------------------------------------------------
extern "C" void kernel_launch(void* const* d_in, const int* in_sizes, int n_in,
                              void* d_out, int out_size) {
    (void)in_sizes; (void)n_in; (void)out_size;
    const float* x       = (const float*)d_in[0];
    const float* norm1_g = (const float*)d_in[2];
    const float* norm1_b = (const float*)d_in[3];
    const float* qkv_w   = (const float*)d_in[4];
    const float* qkv_b   = (const float*)d_in[5];
    const float* proj_w  = (const float*)d_in[6];
    const float* proj_b  = (const float*)d_in[7];
    const float* norm2_g = (const float*)d_in[8];
    const float* norm2_b = (const float*)d_in[9];
    const float* fc1_w   = (const float*)d_in[10];
    const float* fc1_b   = (const float*)d_in[11];
    const float* fc2_w   = (const float*)d_in[12];
    const float* fc2_b   = (const float*)d_in[13];
    float* out = (float*)d_out;

    void *qkv16p, *attn16p, *h16p, *x2p, *wbp;
    cudaGetSymbolAddress(&qkv16p,  g_qkv16b);
    cudaGetSymbolAddress(&attn16p, g_attn16b);
    cudaGetSymbolAddress(&h16p,    g_h16b);
    cudaGetSymbolAddress(&x2p,     g_x2b);
    cudaGetSymbolAddress(&wbp,     g_wbb);
    __nv_bfloat16* qkv16  = (__nv_bfloat16*)qkv16p;
    __nv_bfloat16* attn16 = (__nv_bfloat16*)attn16p;
    __nv_bfloat16* h16    = (__nv_bfloat16*)h16p;
    float*         x2     = (float*)x2p;
    __nv_bfloat16* wb     = (__nv_bfloat16*)wbp;

    const int bf_smem_ln = (128 * AW + 3 * WCW) * 4 + 128 * FSW * 4;  // 100864 B
    const int bf_smem    = (128 * AW + 3 * WCW) * 4;                  //  49664 B
    const int fc2_smem   = 3 * (128 * WRW + 96 * WRW) * 4;            //  53760 B
    cudaFuncSetAttribute(gemm_bf<EPI_QKV,  true,  true,  3>, cudaFuncAttributeMaxDynamicSharedMemorySize, bf_smem_ln);
    cudaFuncSetAttribute(gemm_bf<EPI_PROJ, false, false, 1>, cudaFuncAttributeMaxDynamicSharedMemorySize, bf_smem);
    cudaFuncSetAttribute(gemm_bf<EPI_FC1,  true,  false, 4>, cudaFuncAttributeMaxDynamicSharedMemorySize, bf_smem_ln);
    cudaFuncSetAttribute(gemm_fc2b, cudaFuncAttributeMaxDynamicSharedMemorySize, fc2_smem);

    const int attn_smem = (256 * QSTR * 2 + 256 * 24 + 256 * PSTR + 512 + 64) * 4;
    cudaFuncSetAttribute(attn_mma, cudaFuncAttributeMaxDynamicSharedMemorySize, attn_smem);

    // 0) convert all weights to bf16
    cvt_w<<<216, 256>>>(qkv_w, proj_w, fc1_w, fc2_w);
    // 1) QKV: fused LN1 + shift + partition; bf16 mma; bf16 out
    gemm_bf<EPI_QKV, true, true, 3><<<1024, 256, bf_smem_ln>>>(
        x, wb + WOFF_QKV, qkv_b, nullptr, norm1_g, norm1_b, qkv16);
    // 2) windowed attention (tf32 internals, bf16 I/O)
    attn_mma<<<dim3(NWIN, NHEADS), 256, attn_smem>>>(qkv16, attn16);
    // 3) proj + reverse shift + residual (fp32 trunk out)
    gemm_bf<EPI_PROJ, false, false, 1><<<1024, 256, bf_smem>>>(
        attn16, wb + WOFF_PROJ, proj_b, x, nullptr, nullptr, x2);
    // 4) fc1: fused LN2 + fast GELU; bf16 out
    gemm_bf<EPI_FC1, true, false, 4><<<1024, 256, bf_smem_ln>>>(
        x2, wb + WOFF_FC1, fc1_b, nullptr, norm2_g, norm2_b, h16);
    // 5) fc2 + residual -> fp32 output
    gemm_fc2b<<<1024, 256, fc2_smem>>>(h16, wb + WOFF_FC2, fc2_b, x2, out);
}

// round 17
// speedup vs baseline: 1.4524x; 1.0295x over previous
#include <cuda_runtime.h>
#include <cuda_bf16.h>
#include <cstdint>
#include <cstddef>

#define TOKENS   131072
#define CDIM     96
#define NWIN     512
#define NTOK     256
#define HD       24
#define NHEADS   4
#define HIDDEN_DIM 384

typedef unsigned long long ull;

// Scratch (device globals; float4 for 16B alignment)
__device__ float4 g_qkv16b [4718592];   // 3*T*C bf16
__device__ float4 g_attn16b[1572864];   // T*C bf16
__device__ float4 g_h16b   [6291456];   // T*HIDDEN bf16
__device__ float4 g_x2b    [3145728];   // T*C fp32 (residual trunk)
__device__ float4 g_wbb    [13824];     // 110592 bf16 weights: qkv|proj|fc1|fc2

#define WOFF_QKV 0
#define WOFF_PROJ 27648
#define WOFF_FC1 36864
#define WOFF_FC2 73728

__device__ __forceinline__ int nat_index(int t) {
    int r = t & 255, w = t >> 8;
    int b = w >> 8, wi = w & 255;
    int d  = ((((wi >> 6) & 3) << 2) | ((r >> 6) & 3));
    int hh = ((((wi >> 4) & 3) << 2) | ((r >> 4) & 3));
    int ww = ((((wi >> 2) & 3) << 2) | ((r >> 2) & 3));
    int tt = (((wi & 3) << 2) | (r & 3));
    d = (d + 2) & 15; hh = (hh + 2) & 15; ww = (ww + 2) & 15; tt = (tt + 2) & 15;
    return (((b * 16 + d) * 16 + hh) * 16 + ww) * 16 + tt;
}

__device__ __forceinline__ int group_of(int wi, int r) {
    int g = 0;
#pragma unroll
    for (int a = 3; a >= 0; --a) {
        int c = ((((wi >> (2 * a)) & 3) << 2) | ((r >> (2 * a)) & 3));
        int s = (c < 12) ? 0 : ((c < 14) ? 1 : 2);
        g = g * 3 + s;
    }
    return g;
}

__device__ __forceinline__ void mma_bf16(float4& d, const uint32_t a[4], const uint32_t b[2]) {
    asm("mma.sync.aligned.m16n8k16.row.col.f32.bf16.bf16.f32 "
        "{%0,%1,%2,%3},{%4,%5,%6,%7},{%8,%9},{%0,%1,%2,%3};"
        : "+f"(d.x), "+f"(d.y), "+f"(d.z), "+f"(d.w)
        : "r"(a[0]), "r"(a[1]), "r"(a[2]), "r"(a[3]), "r"(b[0]), "r"(b[1]));
}

// cp.async helpers
__device__ __forceinline__ void cp16(uint32_t dst, const void* src) {
    asm volatile("cp.async.cg.shared.global [%0],[%1],16;" :: "r"(dst), "l"(src));
}
__device__ __forceinline__ void cp_commit() { asm volatile("cp.async.commit_group;"); }
template <int N>
__device__ __forceinline__ void cp_wait() { asm volatile("cp.async.wait_group %0;" :: "n"(N)); }

__device__ __forceinline__ uint32_t bf2u(float a, float b) {
    __nv_bfloat162 t = __floats2bfloat162_rn(a, b);
    return *(uint32_t*)&t;
}

// Fast exact-enough GELU (Abramowitz-Stegun 7.1.26 erf, |err|<=1.5e-7).
__device__ __forceinline__ float gelu_f(float v) {
    float z = fabsf(v) * 0.70710678118654752f;
    float t = __frcp_rn(fmaf(0.3275911f, z, 1.f));
    float p = fmaf(fmaf(fmaf(fmaf(1.061405429f, t, -1.453152027f), t, 1.421413741f),
                        t, -0.284496736f), t, 0.254829592f) * t;
    float e = __expf(-z * z);
    float er = copysignf(fmaf(-p, e, 1.f), v);
    return 0.5f * v * (1.f + er);
}

enum { EPI_QKV = 0, EPI_PROJ = 1, EPI_FC1 = 2 };

// ---------------------------------------------------------------------------
// Weight fp32->bf16 conversion.
// ---------------------------------------------------------------------------
__global__ void cvt_w(const float* __restrict__ qw, const float* __restrict__ pw,
                      const float* __restrict__ f1, const float* __restrict__ f2) {
    int i = blockIdx.x * 256 + threadIdx.x;
    if (i >= 55296) return;
    int e = i * 2;
    const float* src; int off;
    if (e < WOFF_PROJ)      { src = qw; off = e; }
    else if (e < WOFF_FC1)  { src = pw; off = e - WOFF_PROJ; }
    else if (e < WOFF_FC2)  { src = f1; off = e - WOFF_FC1; }
    else                    { src = f2; off = e - WOFF_FC2; }
    float2 v = *(const float2*)(src + off);
    ((uint32_t*)g_wbb)[i] = bf2u(v.x, v.y);
}

// ---------------------------------------------------------------------------
// bf16 GEMM (K=96), A-resident + 3-stage W ring, single sync per chunk.
// (used for qkv and fc1)
// ---------------------------------------------------------------------------
#define AW   52
#define WRW  20
#define WCW  (96 * WRW)
#define FSW  100

template <int E, bool LNF, bool GATHER, int NB>
__global__ void __launch_bounds__(256, 2) gemm_bf(const void* __restrict__ Ain,
                                                  const __nv_bfloat16* __restrict__ W,
                                                  const float* __restrict__ bias,
                                                  const float* __restrict__ res,
                                                  const float* __restrict__ gamma,
                                                  const float* __restrict__ beta,
                                                  void* __restrict__ outv) {
    extern __shared__ uint32_t sw[];
    uint32_t* Ab   = sw;
    uint32_t* ring = sw + 128 * AW;
    float*    Fs   = (float*)(sw + 128 * AW + 3 * WCW);
    constexpr int NC = NB * 3;

    const int tid  = threadIdx.x;
    const int warp = tid >> 5, lane = tid & 31;
    const int gid  = lane >> 2, tig = lane & 3;
    const int wm   = (warp >> 1) * 32;
    const int wb   = warp & 1;
    const int wn   = wb * 48;
    const int m0   = blockIdx.x * 128;

    uint32_t ab_u   = (uint32_t)__cvta_generic_to_shared(Ab);
    uint32_t ring_u = (uint32_t)__cvta_generic_to_shared(ring);
    uint32_t fs_u   = (uint32_t)__cvta_generic_to_shared(Fs);

    if (LNF) {
        const float* Afp = (const float*)Ain;
#pragma unroll
        for (int it = 0; it < 12; ++it) {
            int idx = tid + it * 256;
            int row = idx / 24, c4 = (idx % 24) << 2;
            int m = m0 + row;
            cp16(fs_u + (row * FSW + c4) * 4,
                 Afp + (size_t)(GATHER ? nat_index(m) : m) * CDIM + c4);
        }
    } else {
        const __nv_bfloat16* Abf = (const __nv_bfloat16*)Ain;
#pragma unroll
        for (int it = 0; it < 6; ++it) {
            int idx = tid + it * 256;
            int row = idx / 12, ch = idx % 12;
            cp16(ab_u + (row * AW + ch * 4) * 4,
                 Abf + (size_t)(m0 + row) * CDIM + ch * 8);
        }
    }
    cp_commit();

    auto issueW = [&](int c) {
        int st = c % 3, n0 = (c / 3) * 96, kc = (c % 3) * 32;
        uint32_t wbuf = ring_u + (st * WCW) * 4;
#pragma unroll
        for (int it = 0; it < 2; ++it) {
            int idx = tid + it * 256;
            if (idx < 384) {
                int row = idx >> 2, ch = idx & 3;
                cp16(wbuf + (row * WRW + ch * 4) * 4,
                     W + (size_t)(n0 + row) * CDIM + kc + ch * 8);
            }
        }
    };
    issueW(0); cp_commit();
    issueW(1); cp_commit();

    if (LNF) {
        cp_wait<2>();
        __syncthreads();
        int row = tid >> 1, half = tid & 1;
        float s = 0.f, sq = 0.f;
#pragma unroll
        for (int i = 0; i < 48; ++i) {
            float v = Fs[row * FSW + half * 48 + i];
            s += v; sq += v * v;
        }
        s  += __shfl_xor_sync(0xffffffffu, s, 1);
        sq += __shfl_xor_sync(0xffffffffu, sq, 1);
        float mean = s * (1.f / 96.f);
        float var  = sq * (1.f / 96.f) - mean * mean;
        float rstd = rsqrtf(var + 1e-5f);
#pragma unroll
        for (int i = 0; i < 24; ++i) {
            int c0 = half * 48 + 2 * i;
            float v0 = (Fs[row * FSW + c0]     - mean) * rstd * __ldg(gamma + c0)     + __ldg(beta + c0);
            float v1 = (Fs[row * FSW + c0 + 1] - mean) * rstd * __ldg(gamma + c0 + 1) + __ldg(beta + c0 + 1);
            Ab[row * AW + half * 24 + i] = bf2u(v0, v1);
        }
    }

    float4 acc[2][6];
#pragma unroll
    for (int i = 0; i < 2; ++i)
#pragma unroll
        for (int j = 0; j < 6; ++j) acc[i][j] = make_float4(0.f, 0.f, 0.f, 0.f);

    for (int c = 0; c < NC; ++c) {
        cp_wait<1>();
        __syncthreads();
        if (c + 2 < NC) issueW(c + 2);
        cp_commit();

        const uint32_t* Ws = ring + (c % 3) * WCW;
        const int kwb = (c % 3) * 16;

#pragma unroll
        for (int ks = 0; ks < 2; ++ks) {
            const int kw = kwb + ks * 8;
            const int wk = ks * 8;
            uint32_t a[2][4];
#pragma unroll
            for (int mi = 0; mi < 2; ++mi) {
                int r = wm + mi * 16 + gid;
                a[mi][0] = Ab[r * AW + kw + tig];
                a[mi][1] = Ab[(r + 8) * AW + kw + tig];
                a[mi][2] = Ab[r * AW + kw + tig + 4];
                a[mi][3] = Ab[(r + 8) * AW + kw + tig + 4];
            }
            uint32_t b[6][2];
#pragma unroll
            for (int ni = 0; ni < 6; ++ni) {
                int n = wn + ni * 8 + gid;
                b[ni][0] = Ws[n * WRW + wk + tig];
                b[ni][1] = Ws[n * WRW + wk + tig + 4];
            }
#pragma unroll
            for (int mi = 0; mi < 2; ++mi)
#pragma unroll
                for (int ni = 0; ni < 6; ++ni) mma_bf16(acc[mi][ni], a[mi], b[ni]);
        }

        if ((c % 3) == 2) {
            const int nb = c / 3, n0 = nb * 96;
#pragma unroll
            for (int mi = 0; mi < 2; ++mi) {
                int r0 = m0 + wm + mi * 16 + gid;
#pragma unroll
                for (int half = 0; half < 2; ++half) {
                    int m = r0 + half * 8;
                    int w = m >> 8, rr = m & 255;
#pragma unroll
                    for (int ni = 0; ni < 6; ++ni) {
                        float v0 = half ? acc[mi][ni].z : acc[mi][ni].x;
                        float v1 = half ? acc[mi][ni].w : acc[mi][ni].y;
                        int nl = wn + ni * 8 + tig * 2;
                        v0 += bias[n0 + nl];
                        v1 += bias[n0 + nl + 1];
                        if (E == EPI_QKV) {
                            const float sc = (nb == 0) ? 0.20412414523193154f : 1.0f;
                            int hh = nl / 24, dd = nl % 24;
                            __nv_bfloat16* ob = (__nv_bfloat16*)outv;
                            *(uint32_t*)(ob + (((size_t)nb * NWIN + w) * NHEADS + hh) * (NTOK * HD) + rr * HD + dd)
                                = bf2u(v0 * sc, v1 * sc);
                        } else {  // EPI_FC1
                            __nv_bfloat16* ob = (__nv_bfloat16*)outv;
                            *(uint32_t*)(ob + (size_t)m * HIDDEN_DIM + n0 + nl)
                                = bf2u(gelu_f(v0), gelu_f(v1));
                        }
                    }
                }
            }
            if (c + 1 < NC) {
#pragma unroll
                for (int i = 0; i < 2; ++i)
#pragma unroll
                    for (int j = 0; j < 6; ++j) acc[i][j] = make_float4(0.f, 0.f, 0.f, 0.f);
            }
        }
    }
}

// ---------------------------------------------------------------------------
// proj: W-RESIDENT bf16 GEMM, 4 m-tiles/CTA, 3-buffer A ring.
// Group accounting: G0=W, G_i = A_{i-1}, one commit per iter.  At iter mt,
// commits = 3+mt; cp_wait<1> completes through G_{mt+1} = A_mt.  (R16 bug:
// wait<2> only guaranteed A_{mt-1} -> read of in-flight tile -> NaN.)
// ---------------------------------------------------------------------------
#define MIT 4

__global__ void __launch_bounds__(256, 2) gemm_projw(const __nv_bfloat16* __restrict__ A,
                                                     const __nv_bfloat16* __restrict__ W,
                                                     const float* __restrict__ bias,
                                                     const float* __restrict__ res,
                                                     float* __restrict__ out) {
    extern __shared__ uint32_t sw[];
    uint32_t* Wr = sw;                    // [96][52]
    uint32_t* Ab = sw + 96 * AW;          // 3 x [128][52]
    constexpr int ABUF = 128 * AW;

    const int tid  = threadIdx.x;
    const int warp = tid >> 5, lane = tid & 31;
    const int gid  = lane >> 2, tig = lane & 3;
    const int wm   = (warp >> 1) * 32;
    const int wb   = warp & 1;
    const int wn   = wb * 48;
    const int mbase = blockIdx.x * (MIT * 128);

    uint32_t wr_u = (uint32_t)__cvta_generic_to_shared(Wr);
    uint32_t ab_u = (uint32_t)__cvta_generic_to_shared(Ab);

    // group 0: resident W (96x96 bf16 = 1152 cp16)
#pragma unroll
    for (int it = 0; it < 5; ++it) {
        int idx = tid + it * 256;
        if (idx < 1152) {
            int row = idx / 12, ch = idx % 12;
            cp16(wr_u + (row * AW + ch * 4) * 4, W + (size_t)row * CDIM + ch * 8);
        }
    }
    cp_commit();

    auto issueA = [&](int mt) {
        uint32_t abuf = ab_u + ((mt % 3) * ABUF) * 4;
        const __nv_bfloat16* src = A + (size_t)(mbase + mt * 128) * CDIM;
#pragma unroll
        for (int it = 0; it < 6; ++it) {
            int idx = tid + it * 256;
            int row = idx / 12, ch = idx % 12;
            cp16(abuf + (row * AW + ch * 4) * 4, src + (size_t)row * CDIM + ch * 8);
        }
    };
    issueA(0); cp_commit();
    issueA(1); cp_commit();

    for (int mt = 0; mt < MIT; ++mt) {
        cp_wait<1>();                     // complete through A_mt (fixed from <2>)
        __syncthreads();                  // prior readers of stage (mt+2)%3 done
        if (mt + 2 < MIT) issueA(mt + 2);
        cp_commit();

        const uint32_t* As = Ab + (mt % 3) * ABUF;

        float4 acc[2][6];
#pragma unroll
        for (int i = 0; i < 2; ++i)
#pragma unroll
            for (int j = 0; j < 6; ++j) acc[i][j] = make_float4(0.f, 0.f, 0.f, 0.f);

#pragma unroll
        for (int ks = 0; ks < 6; ++ks) {
            const int kw = ks * 8;
            uint32_t a[2][4];
#pragma unroll
            for (int mi = 0; mi < 2; ++mi) {
                int r = wm + mi * 16 + gid;
                a[mi][0] = As[r * AW + kw + tig];
                a[mi][1] = As[(r + 8) * AW + kw + tig];
                a[mi][2] = As[r * AW + kw + tig + 4];
                a[mi][3] = As[(r + 8) * AW + kw + tig + 4];
            }
            uint32_t b[6][2];
#pragma unroll
            for (int ni = 0; ni < 6; ++ni) {
                int n = wn + ni * 8 + gid;
                b[ni][0] = Wr[n * AW + kw + tig];
                b[ni][1] = Wr[n * AW + kw + tig + 4];
            }
#pragma unroll
            for (int mi = 0; mi < 2; ++mi)
#pragma unroll
                for (int ni = 0; ni < 6; ++ni) mma_bf16(acc[mi][ni], a[mi], b[ni]);
        }

        const int m0 = mbase + mt * 128;
#pragma unroll
        for (int mi = 0; mi < 2; ++mi) {
            int r0 = m0 + wm + mi * 16 + gid;
#pragma unroll
            for (int half = 0; half < 2; ++half) {
                int m = r0 + half * 8;
                size_t dst = (size_t)nat_index(m) * CDIM;
#pragma unroll
                for (int ni = 0; ni < 6; ++ni) {
                    float v0 = half ? acc[mi][ni].z : acc[mi][ni].x;
                    float v1 = half ? acc[mi][ni].w : acc[mi][ni].y;
                    int nl = wn + ni * 8 + tig * 2;
                    out[dst + nl]     = res[dst + nl]     + v0 + bias[nl];
                    out[dst + nl + 1] = res[dst + nl + 1] + v1 + bias[nl + 1];
                }
            }
        }
    }
}

// ---------------------------------------------------------------------------
// bf16 streaming GEMM for fc2 (unchanged).
// ---------------------------------------------------------------------------
__global__ void __launch_bounds__(256, 2) gemm_fc2b(const __nv_bfloat16* __restrict__ A,
                                                    const __nv_bfloat16* __restrict__ W,
                                                    const float* __restrict__ bias,
                                                    const float* __restrict__ res,
                                                    float* __restrict__ out) {
    extern __shared__ uint32_t sw[];
    constexpr int ACHW = 128 * WRW, WCHW = 96 * WRW, STG = ACHW + WCHW;
    constexpr int KD = HIDDEN_DIM, NC = KD / 32;

    const int tid  = threadIdx.x;
    const int warp = tid >> 5, lane = tid & 31;
    const int gid  = lane >> 2, tig = lane & 3;
    const int wm   = (warp >> 1) * 32;
    const int wb   = warp & 1;
    const int wn   = wb * 48;
    const int m0   = blockIdx.x * 128;

    uint32_t sw_u = (uint32_t)__cvta_generic_to_shared(sw);

    auto issue = [&](int c) {
        int st = c % 3, kc = c * 32;
        uint32_t abuf = sw_u + (st * STG) * 4;
#pragma unroll
        for (int it = 0; it < 2; ++it) {
            int idx = tid + it * 256;
            int row = idx >> 2, ch = idx & 3;
            cp16(abuf + (row * WRW + ch * 4) * 4,
                 A + (size_t)(m0 + row) * KD + kc + ch * 8);
        }
        uint32_t wbuf = abuf + ACHW * 4;
#pragma unroll
        for (int it = 0; it < 2; ++it) {
            int idx = tid + it * 256;
            if (idx < 384) {
                int row = idx >> 2, ch = idx & 3;
                cp16(wbuf + (row * WRW + ch * 4) * 4,
                     W + (size_t)row * KD + kc + ch * 8);
            }
        }
    };

    issue(0); cp_commit();
    issue(1); cp_commit();

    float4 acc[2][6];
#pragma unroll
    for (int i = 0; i < 2; ++i)
#pragma unroll
        for (int j = 0; j < 6; ++j) acc[i][j] = make_float4(0.f, 0.f, 0.f, 0.f);

    for (int c = 0; c < NC; ++c) {
        cp_wait<1>();
        __syncthreads();
        if (c + 2 < NC) issue(c + 2);
        cp_commit();

        const uint32_t* As = sw + (c % 3) * STG;
        const uint32_t* Ws = sw + (c % 3) * STG + ACHW;

#pragma unroll
        for (int ks = 0; ks < 2; ++ks) {
            const int kw = ks * 8;
            uint32_t a[2][4];
#pragma unroll
            for (int mi = 0; mi < 2; ++mi) {
                int r = wm + mi * 16 + gid;
                a[mi][0] = As[r * WRW + kw + tig];
                a[mi][1] = As[(r + 8) * WRW + kw + tig];
                a[mi][2] = As[r * WRW + kw + tig + 4];
                a[mi][3] = As[(r + 8) * WRW + kw + tig + 4];
            }
            uint32_t b[6][2];
#pragma unroll
            for (int ni = 0; ni < 6; ++ni) {
                int n = wn + ni * 8 + gid;
                b[ni][0] = Ws[n * WRW + kw + tig];
                b[ni][1] = Ws[n * WRW + kw + tig + 4];
            }
#pragma unroll
            for (int mi = 0; mi < 2; ++mi)
#pragma unroll
                for (int ni = 0; ni < 6; ++ni) mma_bf16(acc[mi][ni], a[mi], b[ni]);
        }
    }

#pragma unroll
    for (int mi = 0; mi < 2; ++mi) {
        int r0 = m0 + wm + mi * 16 + gid;
#pragma unroll
        for (int half = 0; half < 2; ++half) {
            int m = r0 + half * 8;
#pragma unroll
            for (int ni = 0; ni < 6; ++ni) {
                float v0 = half ? acc[mi][ni].z : acc[mi][ni].x;
                float v1 = half ? acc[mi][ni].w : acc[mi][ni].y;
                int nl = wn + ni * 8 + tig * 2;
                out[(size_t)m * CDIM + nl]     = res[(size_t)m * CDIM + nl]     + v0 + bias[nl];
                out[(size_t)m * CDIM + nl + 1] = res[(size_t)m * CDIM + nl + 1] + v1 + bias[nl + 1];
            }
        }
    }
}

// ---------------------------------------------------------------------------
// bf16 tensor-core attention. Q/K bf16 rows (K=24 padded to 32, stride 20w);
// P packed bf16x2 (fp32 row-sums pre-pack); V transposed (Vt[dim][key-pair]).
// ---------------------------------------------------------------------------
#define QW 20
#define VW 132
#define PW 36
#define QB_OFF 0
#define KB_OFF (256 * QW)
#define VT_OFF (512 * QW)
#define PS_OFF (512 * QW + 24 * VW)
#define LS_OFF (PS_OFF + 256 * PW)
#define ATTN_WORDS (LS_OFF + 512 + 64)   // Ls 512 + grp 64 words (256 B)

__global__ void __launch_bounds__(256) attn_bf(const __nv_bfloat16* __restrict__ qkv,
                                               __nv_bfloat16* __restrict__ attnout) {
    extern __shared__ uint32_t smw[];
    uint32_t* Qb = smw + QB_OFF;
    uint32_t* Kb = smw + KB_OFF;
    uint32_t* Vt = smw + VT_OFF;
    uint32_t* Pb = smw + PS_OFF;
    float*    Ls = (float*)(smw + LS_OFF);
    unsigned char* grp = (unsigned char*)(smw + LS_OFF + 512);

    const int w = blockIdx.x, h = blockIdx.y;
    const int tid = threadIdx.x, warp = tid >> 5, lane = tid & 31;
    const int gid = lane >> 2, tig = lane & 3;
    const int wm = (warp >> 1) * 64;
    const int wb = warp & 1;
    const size_t hs = (size_t)NTOK * HD;
    const __nv_bfloat16* qg = qkv + (((size_t)0 * NWIN + w) * NHEADS + h) * hs;
    const __nv_bfloat16* kg = qkv + (((size_t)1 * NWIN + w) * NHEADS + h) * hs;
    const __nv_bfloat16* vg = qkv + (((size_t)2 * NWIN + w) * NHEADS + h) * hs;

    uint32_t qb_u = (uint32_t)__cvta_generic_to_shared(Qb);
    uint32_t kb_u = (uint32_t)__cvta_generic_to_shared(Kb);

    // Q, K: 256 rows x 3 16B segs each
#pragma unroll
    for (int it = 0; it < 3; ++it) {
        int idx = tid + it * 256;
        int row = idx / 3, seg = idx % 3;
        cp16(qb_u + (row * QW + seg * 4) * 4, qg + row * 24 + seg * 8);
        cp16(kb_u + (row * QW + seg * 4) * 4, kg + row * 24 + seg * 8);
    }
    cp_commit();
    // zero pad words 12..15 (dims 24..31)
#pragma unroll
    for (int j = 0; j < 4; ++j) {
        Qb[tid * QW + 12 + j] = 0;
        Kb[tid * QW + 12 + j] = 0;
    }
    // Vt[n][j] = (V[2j][n], V[2j+1][n]); 24 x 128 words
#pragma unroll
    for (int it = 0; it < 12; ++it) {
        int idx = tid + it * 256;
        int j = idx & 127, n = idx >> 7;
        unsigned short lo = __bfloat16_as_ushort(vg[(2 * j) * 24 + n]);
        unsigned short hi = __bfloat16_as_ushort(vg[(2 * j + 1) * 24 + n]);
        Vt[n * VW + j] = ((uint32_t)hi << 16) | lo;
    }
    grp[tid] = (unsigned char)group_of(w & 255, tid);
    cp_wait<0>();
    __syncthreads();

    float4 oacc[4][3];
#pragma unroll
    for (int i = 0; i < 4; ++i)
#pragma unroll
        for (int j = 0; j < 3; ++j) oacc[i][j] = make_float4(0.f, 0.f, 0.f, 0.f);
    float rs[4][2];
#pragma unroll
    for (int i = 0; i < 4; ++i) { rs[i][0] = 0.f; rs[i][1] = 0.f; }

    for (int kb = 0; kb < 4; ++kb) {
        float4 sacc[4][4];
#pragma unroll
        for (int i = 0; i < 4; ++i)
#pragma unroll
            for (int j = 0; j < 4; ++j) sacc[i][j] = make_float4(0.f, 0.f, 0.f, 0.f);

        // S = Q K^T : 2 k16-steps
#pragma unroll
        for (int ks = 0; ks < 2; ++ks) {
            const int kw = ks * 8;
            uint32_t a[4][4], b[4][2];
#pragma unroll
            for (int mi = 0; mi < 4; ++mi) {
                int r = wm + mi * 16 + gid;
                a[mi][0] = Qb[r * QW + kw + tig];
                a[mi][1] = Qb[(r + 8) * QW + kw + tig];
                a[mi][2] = Qb[r * QW + kw + tig + 4];
                a[mi][3] = Qb[(r + 8) * QW + kw + tig + 4];
            }
#pragma unroll
            for (int ni = 0; ni < 4; ++ni) {
                int n = kb * 64 + wb * 32 + ni * 8 + gid;
                b[ni][0] = Kb[n * QW + kw + tig];
                b[ni][1] = Kb[n * QW + kw + tig + 4];
            }
#pragma unroll
            for (int mi = 0; mi < 4; ++mi)
#pragma unroll
                for (int ni = 0; ni < 4; ++ni) mma_bf16(sacc[mi][ni], a[mi], b[ni]);
        }

        // mask + exp (fp32), row-sum partials (fp32), pack P -> bf16x2
#pragma unroll
        for (int mi = 0; mi < 4; ++mi) {
            int r0 = wm + mi * 16 + gid;
            int rg0 = grp[r0], rg1 = grp[r0 + 8];
#pragma unroll
            for (int ni = 0; ni < 4; ++ni) {
                int cc = kb * 64 + wb * 32 + ni * 8 + 2 * tig;
                int cg0 = grp[cc], cg1 = grp[cc + 1];
                float4 s = sacc[mi][ni];
                float p00 = __expf(s.x + (cg0 == rg0 ? 0.f : -100.f));
                float p01 = __expf(s.y + (cg1 == rg0 ? 0.f : -100.f));
                float p10 = __expf(s.z + (cg0 == rg1 ? 0.f : -100.f));
                float p11 = __expf(s.w + (cg1 == rg1 ? 0.f : -100.f));
                rs[mi][0] += p00 + p01;
                rs[mi][1] += p10 + p11;
                int pcw = wb * 16 + ni * 4 + tig;
                Pb[r0 * PW + pcw]       = bf2u(p00, p01);
                Pb[(r0 + 8) * PW + pcw] = bf2u(p10, p11);
            }
        }
        __syncwarp();

        // PV : 2 k16-steps over this warp's 32-key slice
#pragma unroll
        for (int kk = 0; kk < 2; ++kk) {
            const int kp  = wb * 16 + kk * 8;
            const int kvw = kb * 32 + wb * 16 + kk * 8;
            uint32_t a[4][4], b[3][2];
#pragma unroll
            for (int mi = 0; mi < 4; ++mi) {
                int r = wm + mi * 16 + gid;
                a[mi][0] = Pb[r * PW + kp + tig];
                a[mi][1] = Pb[(r + 8) * PW + kp + tig];
                a[mi][2] = Pb[r * PW + kp + tig + 4];
                a[mi][3] = Pb[(r + 8) * PW + kp + tig + 4];
            }
#pragma unroll
            for (int nd = 0; nd < 3; ++nd) {
                int n = nd * 8 + gid;
                b[nd][0] = Vt[n * VW + kvw + tig];
                b[nd][1] = Vt[n * VW + kvw + tig + 4];
            }
#pragma unroll
            for (int mi = 0; mi < 4; ++mi)
#pragma unroll
                for (int nd = 0; nd < 3; ++nd) mma_bf16(oacc[mi][nd], a[mi], b[nd]);
        }
        __syncwarp();
    }

    // row-sum reduce, publish per-k-half
#pragma unroll
    for (int mi = 0; mi < 4; ++mi)
#pragma unroll
        for (int hf = 0; hf < 2; ++hf) {
            float v = rs[mi][hf];
            v += __shfl_xor_sync(0xffffffffu, v, 1);
            v += __shfl_xor_sync(0xffffffffu, v, 2);
            rs[mi][hf] = v;
        }
    if (tig == 0) {
#pragma unroll
        for (int mi = 0; mi < 4; ++mi) {
            Ls[wb * 256 + wm + mi * 16 + gid]     = rs[mi][0];
            Ls[wb * 256 + wm + mi * 16 + gid + 8] = rs[mi][1];
        }
    }
    __syncthreads();

    // combine two k-half PV partials (Q/K area dead; reuse as fp32 buffer)
    float* OS = (float*)smw;
    const int OSTR = 26;
    if (wb == 1) {
#pragma unroll
        for (int mi = 0; mi < 4; ++mi) {
            int r0 = wm + mi * 16 + gid;
#pragma unroll
            for (int nd = 0; nd < 3; ++nd) {
                int c = nd * 8 + 2 * tig;
                *(float2*)(OS + r0 * OSTR + c)       = make_float2(oacc[mi][nd].x, oacc[mi][nd].y);
                *(float2*)(OS + (r0 + 8) * OSTR + c) = make_float2(oacc[mi][nd].z, oacc[mi][nd].w);
            }
        }
    }
    __syncthreads();
    if (wb == 0) {
#pragma unroll
        for (int mi = 0; mi < 4; ++mi) {
            int r0 = wm + mi * 16 + gid, r1 = r0 + 8;
            float inv0 = 1.f / (Ls[r0] + Ls[256 + r0]);
            float inv1 = 1.f / (Ls[r1] + Ls[256 + r1]);
#pragma unroll
            for (int nd = 0; nd < 3; ++nd) {
                int c = nd * 8 + 2 * tig;
                float2 t0 = *(float2*)(OS + r0 * OSTR + c);
                float2 t1 = *(float2*)(OS + r1 * OSTR + c);
                *(uint32_t*)(attnout + ((size_t)w * NTOK + r0) * CDIM + h * HD + c)
                    = bf2u((oacc[mi][nd].x + t0.x) * inv0, (oacc[mi][nd].y + t0.y) * inv0);
                *(uint32_t*)(attnout + ((size_t)w * NTOK + r1) * CDIM + h * HD + c)
                    = bf2u((oacc[mi][nd].z + t1.x) * inv1, (oacc[mi][nd].w + t1.y) * inv1);
            }
        }
    }
}

// ---------------------------------------------------------------------------
extern "C" void kernel_launch(void* const* d_in, const int* in_sizes, int n_in,
                              void* d_out, int out_size) {
    (void)in_sizes; (void)n_in; (void)out_size;
    const float* x       = (const float*)d_in[0];
    const float* norm1_g = (const float*)d_in[2];
    const float* norm1_b = (const float*)d_in[3];
    const float* qkv_w   = (const float*)d_in[4];
    const float* qkv_b   = (const float*)d_in[5];
    const float* proj_w  = (const float*)d_in[6];
    const float* proj_b  = (const float*)d_in[7];
    const float* norm2_g = (const float*)d_in[8];
    const float* norm2_b = (const float*)d_in[9];
    const float* fc1_w   = (const float*)d_in[10];
    const float* fc1_b   = (const float*)d_in[11];
    const float* fc2_w   = (const float*)d_in[12];
    const float* fc2_b   = (const float*)d_in[13];
    float* out = (float*)d_out;

    void *qkv16p, *attn16p, *h16p, *x2p, *wbp;
    cudaGetSymbolAddress(&qkv16p,  g_qkv16b);
    cudaGetSymbolAddress(&attn16p, g_attn16b);
    cudaGetSymbolAddress(&h16p,    g_h16b);
    cudaGetSymbolAddress(&x2p,     g_x2b);
    cudaGetSymbolAddress(&wbp,     g_wbb);
    __nv_bfloat16* qkv16  = (__nv_bfloat16*)qkv16p;
    __nv_bfloat16* attn16 = (__nv_bfloat16*)attn16p;
    __nv_bfloat16* h16    = (__nv_bfloat16*)h16p;
    float*         x2     = (float*)x2p;
    __nv_bfloat16* wb     = (__nv_bfloat16*)wbp;

    const int bf_smem_ln = (128 * AW + 3 * WCW) * 4 + 128 * FSW * 4;  // 100864 B
    const int proj_smem  = (96 * AW + 3 * 128 * AW) * 4;              //  99840 B
    const int fc2_smem   = 3 * (128 * WRW + 96 * WRW) * 4;            //  53760 B
    const int attn_smem  = ATTN_WORDS * 4;                            //  92800 B
    cudaFuncSetAttribute(gemm_bf<EPI_QKV, true, true,  3>, cudaFuncAttributeMaxDynamicSharedMemorySize, bf_smem_ln);
    cudaFuncSetAttribute(gemm_bf<EPI_FC1, true, false, 4>, cudaFuncAttributeMaxDynamicSharedMemorySize, bf_smem_ln);
    cudaFuncSetAttribute(gemm_projw, cudaFuncAttributeMaxDynamicSharedMemorySize, proj_smem);
    cudaFuncSetAttribute(gemm_fc2b, cudaFuncAttributeMaxDynamicSharedMemorySize, fc2_smem);
    cudaFuncSetAttribute(attn_bf, cudaFuncAttributeMaxDynamicSharedMemorySize, attn_smem);

    // 0) weights -> bf16
    cvt_w<<<216, 256>>>(qkv_w, proj_w, fc1_w, fc2_w);
    // 1) QKV: fused LN1 + shift + partition; bf16 out
    gemm_bf<EPI_QKV, true, true, 3><<<1024, 256, bf_smem_ln>>>(
        x, wb + WOFF_QKV, qkv_b, nullptr, norm1_g, norm1_b, qkv16);
    // 2) windowed attention, full bf16 mma path
    attn_bf<<<dim3(NWIN, NHEADS), 256, attn_smem>>>(qkv16, attn16);
    // 3) proj: W-resident, 4 m-tiles/CTA, reverse-shift + residual
    gemm_projw<<<256, 256, proj_smem>>>(attn16, wb + WOFF_PROJ, proj_b, x, x2);
    // 4) fc1: fused LN2 + fast GELU; bf16 out
    gemm_bf<EPI_FC1, true, false, 4><<<1024, 256, bf_smem_ln>>>(
        x2, wb + WOFF_FC1, fc1_b, nullptr, norm2_g, norm2_b, h16);
    // 5) fc2 + residual -> fp32 output
    gemm_fc2b<<<1024, 256, fc2_smem>>>(h16, wb + WOFF_FC2, fc2_b, x2, out);
}